// round 1
// baseline (speedup 1.0000x reference)
#include <cuda_runtime.h>
#include <cstddef>

// ---------------------------------------------------------------------------
// Problem constants
// ---------------------------------------------------------------------------
constexpr int NB = 4096;   // batch
constexpr int ND = 512;    // state dim
constexpr int NH = 2048;   // hidden dim
constexpr int NSTATE = NB * ND;        // 2,097,152
constexpr int NSTEPS = 20;
constexpr int NCORR  = 3;

// ---------------------------------------------------------------------------
// Scratch (device globals; no allocation allowed)
// ---------------------------------------------------------------------------
__device__ float g_y[NSTATE];
__device__ float g_acc[NSTATE];
__device__ float g_ytmp[NSTATE];
__device__ float g_kk[NSTATE];
__device__ float g_pred[NSTATE];
__device__ float g_base[NSTATE];
__device__ float g_hist[4 * NSTATE];
__device__ float g_act[NB * NH];       // tanh activations [4096, 2048]

// ---------------------------------------------------------------------------
// SGEMM: C[M,N] = epilogue(A[M,K] @ B[K,N] + bias[N])
//   MODE 0: C = tanh(acc + bias)
//   MODE 1: C = alpha*(acc + bias) + (addv ? addv : 0)
// 128x128 tile, BK=16, 256 threads, 8x8 per thread (4+4 split), double buffer.
// All dims are multiples of tile sizes here; no bounds checks.
// ---------------------------------------------------------------------------
constexpr int BM = 128, BN = 128, BK = 16;

template <int MODE>
__global__ __launch_bounds__(256)
void sgemm_kernel(const float* __restrict__ A, const float* __restrict__ Bm,
                  float* __restrict__ C, const float* __restrict__ bias,
                  const float* __restrict__ addv, float alpha,
                  int M, int N, int K)
{
    __shared__ float As[2][BK][BM + 4];
    __shared__ float Bs[2][BK][BN];

    const int tid = threadIdx.x;
    const int bm = blockIdx.y * BM;
    const int bn = blockIdx.x * BN;

    // ---- global load mapping (2 float4 of A, 2 float4 of B per thread) ----
    const int a_row = tid >> 2;            // 0..63 (second load +64)
    const int a_col = (tid & 3) * 4;       // 0,4,8,12
    const int b_row = tid >> 5;            // 0..7  (second load +8)
    const int b_col = (tid & 31) * 4;      // 0..124

    const float* Aptr = A + (size_t)bm * K;
    const float* Bptr = Bm + bn;

    float4 ra0, ra1, rb0, rb1;

    auto ldg = [&](int kt) {
        const int k0 = kt * BK;
        ra0 = *(const float4*)(Aptr + (size_t)(a_row     ) * K + k0 + a_col);
        ra1 = *(const float4*)(Aptr + (size_t)(a_row + 64) * K + k0 + a_col);
        rb0 = *(const float4*)(Bptr + (size_t)(k0 + b_row    ) * N + b_col);
        rb1 = *(const float4*)(Bptr + (size_t)(k0 + b_row + 8) * N + b_col);
    };
    auto sts = [&](int buf) {
        As[buf][a_col + 0][a_row]      = ra0.x;
        As[buf][a_col + 1][a_row]      = ra0.y;
        As[buf][a_col + 2][a_row]      = ra0.z;
        As[buf][a_col + 3][a_row]      = ra0.w;
        As[buf][a_col + 0][a_row + 64] = ra1.x;
        As[buf][a_col + 1][a_row + 64] = ra1.y;
        As[buf][a_col + 2][a_row + 64] = ra1.z;
        As[buf][a_col + 3][a_row + 64] = ra1.w;
        *(float4*)&Bs[buf][b_row    ][b_col] = rb0;
        *(float4*)&Bs[buf][b_row + 8][b_col] = rb1;
    };

    // ---- compute mapping: 4+4 split tile ----
    const int tm2 = (tid / 16) * 4;   // rows tm2..tm2+3 and tm2+64..tm2+67
    const int tn2 = (tid % 16) * 4;   // cols tn2..tn2+3 and tn2+64..tn2+67

    float acc[8][8];
    #pragma unroll
    for (int i = 0; i < 8; i++)
        #pragma unroll
        for (int j = 0; j < 8; j++) acc[i][j] = 0.f;

    const int T = K / BK;
    ldg(0);
    sts(0);
    __syncthreads();

    for (int kt = 0; kt < T; kt++) {
        const int cur = kt & 1;
        if (kt + 1 < T) ldg(kt + 1);

        #pragma unroll
        for (int kk = 0; kk < BK; kk++) {
            float4 aA = *(const float4*)&As[cur][kk][tm2];
            float4 aB = *(const float4*)&As[cur][kk][tm2 + 64];
            float4 bA = *(const float4*)&Bs[cur][kk][tn2];
            float4 bB = *(const float4*)&Bs[cur][kk][tn2 + 64];
            float ar[8] = {aA.x, aA.y, aA.z, aA.w, aB.x, aB.y, aB.z, aB.w};
            float br[8] = {bA.x, bA.y, bA.z, bA.w, bB.x, bB.y, bB.z, bB.w};
            #pragma unroll
            for (int i = 0; i < 8; i++)
                #pragma unroll
                for (int j = 0; j < 8; j++)
                    acc[i][j] = fmaf(ar[i], br[j], acc[i][j]);
        }

        if (kt + 1 < T) sts(cur ^ 1);
        __syncthreads();
    }

    // ---- epilogue ----
    #pragma unroll
    for (int i = 0; i < 8; i++) {
        const int row = bm + tm2 + ((i < 4) ? i : (64 + i - 4));
        const size_t rbase = (size_t)row * N;
        #pragma unroll
        for (int half = 0; half < 2; half++) {
            const int col = bn + tn2 + half * 64;
            float4 v;
            v.x = acc[i][half * 4 + 0] + bias[col + 0];
            v.y = acc[i][half * 4 + 1] + bias[col + 1];
            v.z = acc[i][half * 4 + 2] + bias[col + 2];
            v.w = acc[i][half * 4 + 3] + bias[col + 3];
            if (MODE == 0) {
                v.x = tanhf(v.x); v.y = tanhf(v.y);
                v.z = tanhf(v.z); v.w = tanhf(v.w);
            } else {
                if (addv) {
                    float4 av = *(const float4*)&addv[rbase + col];
                    v.x = fmaf(alpha, v.x, av.x);
                    v.y = fmaf(alpha, v.y, av.y);
                    v.z = fmaf(alpha, v.z, av.z);
                    v.w = fmaf(alpha, v.w, av.w);
                } else {
                    v.x *= alpha; v.y *= alpha; v.z *= alpha; v.w *= alpha;
                }
            }
            *(float4*)&C[rbase + col] = v;
        }
    }
}

// ---------------------------------------------------------------------------
// Elementwise kernels (float4, exact-size grids: NSTATE/4 = 2048*256)
// ---------------------------------------------------------------------------
__global__ void k_axpy(float4* __restrict__ o, const float4* __restrict__ y,
                       const float4* __restrict__ k, float a)
{
    int i = blockIdx.x * 256 + threadIdx.x;
    float4 yv = y[i], kv = k[i];
    o[i] = make_float4(fmaf(a, kv.x, yv.x), fmaf(a, kv.y, yv.y),
                       fmaf(a, kv.z, yv.z), fmaf(a, kv.w, yv.w));
}

__global__ void k_acc(float4* __restrict__ o, const float4* __restrict__ p, float a)
{
    int i = blockIdx.x * 256 + threadIdx.x;
    float4 ov = o[i], pv = p[i];
    o[i] = make_float4(fmaf(a, pv.x, ov.x), fmaf(a, pv.y, ov.y),
                       fmaf(a, pv.z, ov.z), fmaf(a, pv.w, ov.w));
}

// pred = y + c*(55 h0 - 59 h1 + 37 h2 - 9 h3)
__global__ void k_pred(float4* __restrict__ o, const float4* __restrict__ y,
                       const float4* __restrict__ h0, const float4* __restrict__ h1,
                       const float4* __restrict__ h2, const float4* __restrict__ h3,
                       float c)
{
    int i = blockIdx.x * 256 + threadIdx.x;
    float4 yv = y[i], a = h0[i], b = h1[i], d = h2[i], e = h3[i];
    float4 r;
    r.x = yv.x + c * (55.f * a.x - 59.f * b.x + 37.f * d.x - 9.f * e.x);
    r.y = yv.y + c * (55.f * a.y - 59.f * b.y + 37.f * d.y - 9.f * e.y);
    r.z = yv.z + c * (55.f * a.z - 59.f * b.z + 37.f * d.z - 9.f * e.z);
    r.w = yv.w + c * (55.f * a.w - 59.f * b.w + 37.f * d.w - 9.f * e.w);
    o[i] = r;
}

// base = y + c*(19 h0 - 5 h1 + h2)
__global__ void k_base(float4* __restrict__ o, const float4* __restrict__ y,
                       const float4* __restrict__ h0, const float4* __restrict__ h1,
                       const float4* __restrict__ h2, float c)
{
    int i = blockIdx.x * 256 + threadIdx.x;
    float4 yv = y[i], a = h0[i], b = h1[i], d = h2[i];
    float4 r;
    r.x = yv.x + c * (19.f * a.x - 5.f * b.x + d.x);
    r.y = yv.y + c * (19.f * a.y - 5.f * b.y + d.y);
    r.z = yv.z + c * (19.f * a.z - 5.f * b.z + d.z);
    r.w = yv.w + c * (19.f * a.w - 5.f * b.w + d.w);
    o[i] = r;
}

// ---------------------------------------------------------------------------
// Host orchestration
// ---------------------------------------------------------------------------
extern "C" void kernel_launch(void* const* d_in, const int* in_sizes, int n_in,
                              void* d_out, int out_size)
{
    const float* x  = (const float*)d_in[0];
    const float* W1 = (const float*)d_in[1];
    const float* b1 = (const float*)d_in[2];
    const float* W2 = (const float*)d_in[3];
    const float* b2 = (const float*)d_in[4];
    float* out = (float*)d_out;

    float *y, *acc, *ytmp, *kk, *pred, *base, *histbase, *act;
    cudaGetSymbolAddress((void**)&y,        g_y);
    cudaGetSymbolAddress((void**)&acc,      g_acc);
    cudaGetSymbolAddress((void**)&ytmp,     g_ytmp);
    cudaGetSymbolAddress((void**)&kk,       g_kk);
    cudaGetSymbolAddress((void**)&pred,     g_pred);
    cudaGetSymbolAddress((void**)&base,     g_base);
    cudaGetSymbolAddress((void**)&histbase, g_hist);
    cudaGetSymbolAddress((void**)&act,      g_act);

    float* h[4];
    for (int i = 0; i < 4; i++) h[i] = histbase + (size_t)i * NSTATE;

    const float dt = 1.0f / (float)NSTEPS;
    const float c  = dt / 24.0f;

    const dim3 blk(256);
    const dim3 grid1(NH / BN, NB / BM);   // layer1: N=2048
    const dim3 grid2(ND / BN, NB / BM);   // layer2: N=512
    const int EG = NSTATE / 4 / 256;      // 2048 blocks, exact

    // f(yin) -> dst, with layer-2 epilogue dst = alpha*(.)+addv
    auto feval = [&](const float* yin, float* dst, float alpha, const float* addv) {
        sgemm_kernel<0><<<grid1, blk>>>(yin, W1, act, b1, nullptr, 1.f, NB, NH, ND);
        sgemm_kernel<1><<<grid2, blk>>>(act, W2, dst, b2, addv, alpha, NB, ND, NH);
    };

    // y = x
    cudaMemcpyAsync(y, x, (size_t)NSTATE * sizeof(float), cudaMemcpyDeviceToDevice);

    // ---- bootstrap: f(y0) -> h[3] ----
    feval(y, h[3], 1.f, nullptr);

    // ---- 3 RK4 steps; k1 reused from the most recent hist entry ----
    for (int s = 0; s < 3; s++) {
        float* k1 = h[3 - s];
        k_axpy<<<EG, blk>>>((float4*)acc,  (const float4*)y, (const float4*)k1, dt / 6.f);
        k_axpy<<<EG, blk>>>((float4*)ytmp, (const float4*)y, (const float4*)k1, 0.5f * dt);
        feval(ytmp, kk, 1.f, nullptr);                                   // k2
        k_acc <<<EG, blk>>>((float4*)acc,  (const float4*)kk, dt / 3.f);
        k_axpy<<<EG, blk>>>((float4*)ytmp, (const float4*)y, (const float4*)kk, 0.5f * dt);
        feval(ytmp, kk, 1.f, nullptr);                                   // k3
        k_acc <<<EG, blk>>>((float4*)acc,  (const float4*)kk, dt / 3.f);
        k_axpy<<<EG, blk>>>((float4*)ytmp, (const float4*)y, (const float4*)kk, dt);
        feval(ytmp, kk, 1.f, nullptr);                                   // k4
        k_acc <<<EG, blk>>>((float4*)acc,  (const float4*)kk, dt / 6.f);
        { float* t = y; y = acc; acc = t; }          // y <- y_new
        feval(y, h[2 - s], 1.f, nullptr);            // hist entry (= next k1)
    }

    // ---- 17 ABM4 predictor-corrector steps ----
    const int NABM = NSTEPS - 3;
    for (int i = 0; i < NABM; i++) {
        k_pred<<<EG, blk>>>((float4*)pred, (const float4*)y,
                            (const float4*)h[0], (const float4*)h[1],
                            (const float4*)h[2], (const float4*)h[3], c);
        k_base<<<EG, blk>>>((float4*)base, (const float4*)y,
                            (const float4*)h[0], (const float4*)h[1],
                            (const float4*)h[2], c);
        for (int j = 0; j < NCORR; j++) {
            const bool last = (i == NABM - 1) && (j == NCORR - 1);
            // pred = base + 9c * f(pred); final iterate writes straight to d_out
            feval(pred, last ? out : pred, 9.f * c, base);
        }
        if (i < NABM - 1) {
            feval(pred, h[3], 1.f, nullptr);         // f_new into oldest slot
            float* t = h[3]; h[3] = h[2]; h[2] = h[1]; h[1] = h[0]; h[0] = t;
            float* t2 = y; y = pred; pred = t2;      // y <- pred
        }
    }
}

// round 3
// speedup vs baseline: 2.7103x; 2.7103x over previous
#include <cuda_runtime.h>
#include <cuda_bf16.h>
#include <cstdint>
#include <cstddef>

// ---------------------------------------------------------------------------
// Problem constants
// ---------------------------------------------------------------------------
constexpr int NB = 4096;   // batch
constexpr int ND = 512;    // state dim
constexpr int NH = 2048;   // hidden dim
constexpr int NSTATE = NB * ND;
constexpr int NSTEPS = 20;
constexpr int NCORR  = 3;

// ---------------------------------------------------------------------------
// Scratch (device globals; no allocation allowed)
// ---------------------------------------------------------------------------
__device__ float g_y[NSTATE];
__device__ float g_acc[NSTATE];
__device__ float g_ytmp[NSTATE];
__device__ float g_kk[NSTATE];
__device__ float g_pred[NSTATE];
__device__ float g_base[NSTATE];
__device__ float g_hist[4 * NSTATE];

__device__ __nv_bfloat16 g_w1t_hi[(size_t)NH * ND];
__device__ __nv_bfloat16 g_w1t_lo[(size_t)NH * ND];
__device__ __nv_bfloat16 g_w2t_hi[(size_t)ND * NH];
__device__ __nv_bfloat16 g_w2t_lo[(size_t)ND * NH];
__device__ __nv_bfloat16 g_act_hi[(size_t)NB * NH];
__device__ __nv_bfloat16 g_act_lo[(size_t)NB * NH];

// ---------------------------------------------------------------------------
// Helpers
// ---------------------------------------------------------------------------
__device__ __forceinline__ uint32_t smem_u32(const void* p) {
    uint32_t a;
    asm("{ .reg .u64 t; cvta.to.shared.u64 t, %1; cvt.u32.u64 %0, t; }"
        : "=r"(a) : "l"(p));
    return a;
}

// SW128 byte swizzle (Swizzle<3,4,3>): conflict-free 16B-granule access
__device__ __forceinline__ uint32_t swz(uint32_t o) {
    return o ^ ((o >> 3) & 0x70);
}

__device__ __forceinline__ void ldmx4(uint32_t r[4], uint32_t addr) {
    asm volatile("ldmatrix.sync.aligned.m8n8.x4.shared.b16 {%0,%1,%2,%3}, [%4];"
                 : "=r"(r[0]), "=r"(r[1]), "=r"(r[2]), "=r"(r[3]) : "r"(addr));
}

__device__ __forceinline__ void mma16816(float d[4], const uint32_t a[4],
                                         uint32_t b0, uint32_t b1) {
    asm volatile(
        "mma.sync.aligned.m16n8k16.row.col.f32.bf16.bf16.f32 "
        "{%0,%1,%2,%3}, {%4,%5,%6,%7}, {%8,%9}, {%0,%1,%2,%3};"
        : "+f"(d[0]), "+f"(d[1]), "+f"(d[2]), "+f"(d[3])
        : "r"(a[0]), "r"(a[1]), "r"(a[2]), "r"(a[3]), "r"(b0), "r"(b1));
}

__device__ __forceinline__ uint32_t pk2(__nv_bfloat16 a, __nv_bfloat16 b) {
    __nv_bfloat162 t = __halves2bfloat162(a, b);
    return *reinterpret_cast<uint32_t*>(&t);
}
__device__ __forceinline__ void split1(float v, __nv_bfloat16& h, __nv_bfloat16& l) {
    h = __float2bfloat16(v);
    l = __float2bfloat16(v - __bfloat162float(h));
}

// ---------------------------------------------------------------------------
// HMMA GEMM: C[M,N] = epi(A[M,K] @ BT[N,K]^T + bias)
//   MODE 0 (layer 1): A fp32 (split on the fly) -> out tanh as bf16 hi/lo planes
//   MODE 1 (layer 2): A bf16 hi/lo planes       -> out fp32 alpha*(.)+bias(+addv)
// CTA 128x128, BK=64 (bf16), 8 warps (4x2, each 32x64), bf16x2-split 3-product.
// SMEM: 4 planes x 128 rows x 128B per stage, double buffered = 128 KB.
// ---------------------------------------------------------------------------
constexpr int GEMM_SMEM = 2 * 4 * 16384;   // 131072

template <int MODE>
__global__ __launch_bounds__(256, 1)
void gemm_mma(const float* __restrict__ Af,
              const __nv_bfloat16* __restrict__ Ahi,
              const __nv_bfloat16* __restrict__ Alo,
              const __nv_bfloat16* __restrict__ Bhi,
              const __nv_bfloat16* __restrict__ Blo,
              const float* __restrict__ bias,
              float* __restrict__ Cf,
              __nv_bfloat16* __restrict__ Chi,
              __nv_bfloat16* __restrict__ Clo,
              const float* __restrict__ addv, float alpha,
              int N, int K)
{
    extern __shared__ char smem[];
    const uint32_t sbase = smem_u32(smem);
    const int tid = threadIdx.x;
    const int wid = tid >> 5, lane = tid & 31;
    const int wm = wid & 3;           // 4 row-blocks of 32
    const int wn = wid >> 2;          // 2 col-blocks of 64
    const int bm = blockIdx.y * 128, bn = blockIdx.x * 128;

    // ---- ldmatrix per-lane base byte offsets (within a 16KB plane) ----
    // A x4 tile (16x16): lanes 0-15 rows, 16-31 rows at k+8
    const uint32_t aoff0 = (uint32_t)(wm * 32 + (lane & 15)) * 128 + ((lane >> 4) * 16);
    // B x4 (n16 x k16): groups of 8 lanes -> (n0-7,k0),(n0-7,k8),(n8-15,k0),(n8-15,k8)
    const int bg = lane >> 3;
    const uint32_t boff0 = (uint32_t)(wn * 64 + (lane & 7) + ((bg & 2) ? 8 : 0)) * 128
                         + ((bg & 1) * 16);

    float acc[2][8][4];
    #pragma unroll
    for (int mt = 0; mt < 2; mt++)
        #pragma unroll
        for (int nt = 0; nt < 8; nt++)
            #pragma unroll
            for (int q = 0; q < 4; q++) acc[mt][nt][q] = 0.f;

    const int T = K >> 6;

    // ---- global-load + STS helpers (SW128-swizzled planes) ----
    float4 av[8];
    uint4  a4h[4], a4l[4], b4h[4], b4l[4];

    auto ldg = [&](int c) {
        const int k0 = c << 6;
        if (MODE == 0) {
            #pragma unroll
            for (int i = 0; i < 8; i++) {
                int idx = i * 256 + tid, r = idx >> 4, c4 = idx & 15;
                av[i] = *(const float4*)(Af + (size_t)(bm + r) * K + k0 + c4 * 4);
            }
        } else {
            #pragma unroll
            for (int i = 0; i < 4; i++) {
                int idx = i * 256 + tid, r = idx >> 3, c8 = idx & 7;
                a4h[i] = *(const uint4*)(Ahi + (size_t)(bm + r) * K + k0 + c8 * 8);
                a4l[i] = *(const uint4*)(Alo + (size_t)(bm + r) * K + k0 + c8 * 8);
            }
        }
        #pragma unroll
        for (int i = 0; i < 4; i++) {
            int idx = i * 256 + tid, r = idx >> 3, c8 = idx & 7;
            b4h[i] = *(const uint4*)(Bhi + (size_t)(bn + r) * K + k0 + c8 * 8);
            b4l[i] = *(const uint4*)(Blo + (size_t)(bn + r) * K + k0 + c8 * 8);
        }
    };

    auto sts = [&](int st) {
        char* s_ah = smem + st * 65536;
        char* s_al = s_ah + 16384;
        char* s_bh = s_al + 16384;
        char* s_bl = s_bh + 16384;
        if (MODE == 0) {
            #pragma unroll
            for (int i = 0; i < 8; i++) {
                int idx = i * 256 + tid, r = idx >> 4, c4 = idx & 15;
                uint32_t off = (uint32_t)r * 128 + c4 * 8;
                __nv_bfloat16 hx, hy, hz, hw, lx, ly, lz, lw;
                split1(av[i].x, hx, lx); split1(av[i].y, hy, ly);
                split1(av[i].z, hz, lz); split1(av[i].w, hw, lw);
                uint2 h2, l2;
                h2.x = pk2(hx, hy); h2.y = pk2(hz, hw);
                l2.x = pk2(lx, ly); l2.y = pk2(lz, lw);
                *(uint2*)(s_ah + swz(off)) = h2;
                *(uint2*)(s_al + swz(off)) = l2;
            }
        } else {
            #pragma unroll
            for (int i = 0; i < 4; i++) {
                int idx = i * 256 + tid, r = idx >> 3, c8 = idx & 7;
                uint32_t off = (uint32_t)r * 128 + c8 * 16;
                *(uint4*)(s_ah + swz(off)) = a4h[i];
                *(uint4*)(s_al + swz(off)) = a4l[i];
            }
        }
        #pragma unroll
        for (int i = 0; i < 4; i++) {
            int idx = i * 256 + tid, r = idx >> 3, c8 = idx & 7;
            uint32_t off = (uint32_t)r * 128 + c8 * 16;
            *(uint4*)(s_bh + swz(off)) = b4h[i];
            *(uint4*)(s_bl + swz(off)) = b4l[i];
        }
    };

    auto compute = [&](int st) {
        const uint32_t sa_h = sbase + st * 65536;
        const uint32_t sa_l = sa_h + 16384;
        const uint32_t sb_h = sa_l + 16384;
        const uint32_t sb_l = sb_h + 16384;
        #pragma unroll
        for (int ks = 0; ks < 4; ks++) {
            const uint32_t kb = ks * 32;
            uint32_t ah[2][4], al2[2][4], bh[4][4], bl[4][4];
            #pragma unroll
            for (int mt = 0; mt < 2; mt++) {
                uint32_t o = aoff0 + (uint32_t)mt * 16 * 128 + kb;
                ldmx4(ah[mt],  sa_h + swz(o));
                ldmx4(al2[mt], sa_l + swz(o));
            }
            #pragma unroll
            for (int np = 0; np < 4; np++) {
                uint32_t o = boff0 + (uint32_t)np * 16 * 128 + kb;
                ldmx4(bh[np], sb_h + swz(o));
                ldmx4(bl[np], sb_l + swz(o));
            }
            #pragma unroll
            for (int mt = 0; mt < 2; mt++)
                #pragma unroll
                for (int nt = 0; nt < 8; nt++) {
                    const int np = nt >> 1, hh = (nt & 1) * 2;
                    mma16816(acc[mt][nt], ah[mt],  bh[np][hh], bh[np][hh + 1]);
                    mma16816(acc[mt][nt], ah[mt],  bl[np][hh], bl[np][hh + 1]);
                    mma16816(acc[mt][nt], al2[mt], bh[np][hh], bh[np][hh + 1]);
                }
        }
    };

    // ---- mainloop: double buffered ----
    ldg(0);
    sts(0);
    __syncthreads();
    for (int c = 0; c < T; c++) {
        if (c + 1 < T) ldg(c + 1);
        compute(c & 1);
        if (c + 1 < T) sts((c + 1) & 1);
        __syncthreads();
    }

    // ---- epilogue straight from accumulator registers ----
    // Accum frag: rows (lane>>2) and +8; cols (lane&3)*2, +1
    const int r0l = lane >> 2, c0l = (lane & 3) * 2;
    #pragma unroll
    for (int mt = 0; mt < 2; mt++) {
        const int rowA = bm + wm * 32 + mt * 16 + r0l;
        #pragma unroll
        for (int nt = 0; nt < 8; nt++) {
            const int col = bn + wn * 64 + nt * 8 + c0l;
            const float2 bb = *(const float2*)(bias + col);
            #pragma unroll
            for (int half = 0; half < 2; half++) {
                const int row = rowA + half * 8;
                float v0 = acc[mt][nt][half * 2 + 0] + bb.x;
                float v1 = acc[mt][nt][half * 2 + 1] + bb.y;
                if (MODE == 0) {
                    v0 = tanhf(v0); v1 = tanhf(v1);
                    __nv_bfloat16 h0, l0, h1, l1;
                    split1(v0, h0, l0); split1(v1, h1, l1);
                    *(uint32_t*)(Chi + (size_t)row * N + col) = pk2(h0, h1);
                    *(uint32_t*)(Clo + (size_t)row * N + col) = pk2(l0, l1);
                } else {
                    v0 *= alpha; v1 *= alpha;
                    if (addv) {
                        float2 a2 = *(const float2*)(addv + (size_t)row * N + col);
                        v0 += a2.x; v1 += a2.y;
                    }
                    *(float2*)(Cf + (size_t)row * N + col) = make_float2(v0, v1);
                }
            }
        }
    }
}

// ---------------------------------------------------------------------------
// Weight transpose + bf16 split: W[K][N] -> T_hi/T_lo[N][K]
// ---------------------------------------------------------------------------
__global__ void k_tsplit(const float* __restrict__ W,
                         __nv_bfloat16* __restrict__ Th,
                         __nv_bfloat16* __restrict__ Tl, int K, int N)
{
    __shared__ float t[32][33];
    const int n0 = blockIdx.x * 32, k0 = blockIdx.y * 32;
    for (int i = threadIdx.y; i < 32; i += 8)
        t[i][threadIdx.x] = W[(size_t)(k0 + i) * N + n0 + threadIdx.x];
    __syncthreads();
    for (int i = threadIdx.y; i < 32; i += 8) {
        float v = t[threadIdx.x][i];
        __nv_bfloat16 h, l;
        split1(v, h, l);
        size_t o = (size_t)(n0 + i) * K + k0 + threadIdx.x;
        Th[o] = h; Tl[o] = l;
    }
}

// ---------------------------------------------------------------------------
// Elementwise kernels (float4, exact-size grids)
// ---------------------------------------------------------------------------
__global__ void k_axpy(float4* __restrict__ o, const float4* __restrict__ y,
                       const float4* __restrict__ k, float a)
{
    int i = blockIdx.x * 256 + threadIdx.x;
    float4 yv = y[i], kv = k[i];
    o[i] = make_float4(fmaf(a, kv.x, yv.x), fmaf(a, kv.y, yv.y),
                       fmaf(a, kv.z, yv.z), fmaf(a, kv.w, yv.w));
}

__global__ void k_acc(float4* __restrict__ o, const float4* __restrict__ p, float a)
{
    int i = blockIdx.x * 256 + threadIdx.x;
    float4 ov = o[i], pv = p[i];
    o[i] = make_float4(fmaf(a, pv.x, ov.x), fmaf(a, pv.y, ov.y),
                       fmaf(a, pv.z, ov.z), fmaf(a, pv.w, ov.w));
}

__global__ void k_pred(float4* __restrict__ o, const float4* __restrict__ y,
                       const float4* __restrict__ h0, const float4* __restrict__ h1,
                       const float4* __restrict__ h2, const float4* __restrict__ h3,
                       float c)
{
    int i = blockIdx.x * 256 + threadIdx.x;
    float4 yv = y[i], a = h0[i], b = h1[i], d = h2[i], e = h3[i];
    float4 r;
    r.x = yv.x + c * (55.f * a.x - 59.f * b.x + 37.f * d.x - 9.f * e.x);
    r.y = yv.y + c * (55.f * a.y - 59.f * b.y + 37.f * d.y - 9.f * e.y);
    r.z = yv.z + c * (55.f * a.z - 59.f * b.z + 37.f * d.z - 9.f * e.z);
    r.w = yv.w + c * (55.f * a.w - 59.f * b.w + 37.f * d.w - 9.f * e.w);
    o[i] = r;
}

__global__ void k_base(float4* __restrict__ o, const float4* __restrict__ y,
                       const float4* __restrict__ h0, const float4* __restrict__ h1,
                       const float4* __restrict__ h2, float c)
{
    int i = blockIdx.x * 256 + threadIdx.x;
    float4 yv = y[i], a = h0[i], b = h1[i], d = h2[i];
    float4 r;
    r.x = yv.x + c * (19.f * a.x - 5.f * b.x + d.x);
    r.y = yv.y + c * (19.f * a.y - 5.f * b.y + d.y);
    r.z = yv.z + c * (19.f * a.z - 5.f * b.z + d.z);
    r.w = yv.w + c * (19.f * a.w - 5.f * b.w + d.w);
    o[i] = r;
}

// ---------------------------------------------------------------------------
// Host orchestration
// ---------------------------------------------------------------------------
extern "C" void kernel_launch(void* const* d_in, const int* in_sizes, int n_in,
                              void* d_out, int out_size)
{
    const float* x  = (const float*)d_in[0];
    const float* W1 = (const float*)d_in[1];
    const float* b1 = (const float*)d_in[2];
    const float* W2 = (const float*)d_in[3];
    const float* b2 = (const float*)d_in[4];
    float* out = (float*)d_out;

    float *y, *acc, *ytmp, *kk, *pred, *base, *histbase;
    __nv_bfloat16 *w1h, *w1l, *w2h, *w2l, *ah, *al;
    cudaGetSymbolAddress((void**)&y,        g_y);
    cudaGetSymbolAddress((void**)&acc,      g_acc);
    cudaGetSymbolAddress((void**)&ytmp,     g_ytmp);
    cudaGetSymbolAddress((void**)&kk,       g_kk);
    cudaGetSymbolAddress((void**)&pred,     g_pred);
    cudaGetSymbolAddress((void**)&base,     g_base);
    cudaGetSymbolAddress((void**)&histbase, g_hist);
    cudaGetSymbolAddress((void**)&w1h,      g_w1t_hi);
    cudaGetSymbolAddress((void**)&w1l,      g_w1t_lo);
    cudaGetSymbolAddress((void**)&w2h,      g_w2t_hi);
    cudaGetSymbolAddress((void**)&w2l,      g_w2t_lo);
    cudaGetSymbolAddress((void**)&ah,       g_act_hi);
    cudaGetSymbolAddress((void**)&al,       g_act_lo);

    cudaFuncSetAttribute(gemm_mma<0>, cudaFuncAttributeMaxDynamicSharedMemorySize, GEMM_SMEM);
    cudaFuncSetAttribute(gemm_mma<1>, cudaFuncAttributeMaxDynamicSharedMemorySize, GEMM_SMEM);

    float* h[4];
    for (int i = 0; i < 4; i++) h[i] = histbase + (size_t)i * NSTATE;

    const float dt = 1.0f / (float)NSTEPS;
    const float c  = dt / 24.0f;

    const dim3 blk(256);
    const dim3 grid1(NH / 128, NB / 128);   // 16 x 32
    const dim3 grid2(ND / 128, NB / 128);   // 4 x 32
    const int EG = NSTATE / 4 / 256;

    // ---- transpose + split weights once per launch ----
    k_tsplit<<<dim3(NH / 32, ND / 32), dim3(32, 8)>>>(W1, w1h, w1l, ND, NH);
    k_tsplit<<<dim3(ND / 32, NH / 32), dim3(32, 8)>>>(W2, w2h, w2l, NH, ND);

    auto feval = [&](const float* yin, float* dstF, float alpha, const float* addv) {
        gemm_mma<0><<<grid1, blk, GEMM_SMEM>>>(yin, nullptr, nullptr, w1h, w1l, b1,
                                               nullptr, ah, al, nullptr, 1.f, NH, ND);
        gemm_mma<1><<<grid2, blk, GEMM_SMEM>>>(nullptr, ah, al, w2h, w2l, b2,
                                               dstF, nullptr, nullptr, addv, alpha, ND, NH);
    };

    cudaMemcpyAsync(y, x, (size_t)NSTATE * sizeof(float), cudaMemcpyDeviceToDevice);

    // ---- bootstrap: f(y0) -> h[3] ----
    feval(y, h[3], 1.f, nullptr);

    // ---- 3 RK4 steps; k1 reused from the most recent hist entry ----
    for (int s = 0; s < 3; s++) {
        float* k1 = h[3 - s];
        k_axpy<<<EG, blk>>>((float4*)acc,  (const float4*)y, (const float4*)k1, dt / 6.f);
        k_axpy<<<EG, blk>>>((float4*)ytmp, (const float4*)y, (const float4*)k1, 0.5f * dt);
        feval(ytmp, kk, 1.f, nullptr);                                   // k2
        k_acc <<<EG, blk>>>((float4*)acc,  (const float4*)kk, dt / 3.f);
        k_axpy<<<EG, blk>>>((float4*)ytmp, (const float4*)y, (const float4*)kk, 0.5f * dt);
        feval(ytmp, kk, 1.f, nullptr);                                   // k3
        k_acc <<<EG, blk>>>((float4*)acc,  (const float4*)kk, dt / 3.f);
        k_axpy<<<EG, blk>>>((float4*)ytmp, (const float4*)y, (const float4*)kk, dt);
        feval(ytmp, kk, 1.f, nullptr);                                   // k4
        k_acc <<<EG, blk>>>((float4*)acc,  (const float4*)kk, dt / 6.f);
        { float* t = y; y = acc; acc = t; }          // y <- y_new
        feval(y, h[2 - s], 1.f, nullptr);            // hist entry (= next k1)
    }

    // ---- 17 ABM4 predictor-corrector steps ----
    const int NABM = NSTEPS - 3;
    for (int i = 0; i < NABM; i++) {
        k_pred<<<EG, blk>>>((float4*)pred, (const float4*)y,
                            (const float4*)h[0], (const float4*)h[1],
                            (const float4*)h[2], (const float4*)h[3], c);
        k_base<<<EG, blk>>>((float4*)base, (const float4*)y,
                            (const float4*)h[0], (const float4*)h[1],
                            (const float4*)h[2], c);
        for (int j = 0; j < NCORR; j++) {
            const bool last = (i == NABM - 1) && (j == NCORR - 1);
            feval(pred, last ? out : pred, 9.f * c, base);
        }
        if (i < NABM - 1) {
            feval(pred, h[3], 1.f, nullptr);         // f_new into oldest slot
            float* t = h[3]; h[3] = h[2]; h[2] = h[1]; h[1] = h[0]; h[0] = t;
            float* t2 = y; y = pred; pred = t2;      // y <- pred
        }
    }
}

// round 4
// speedup vs baseline: 3.0436x; 1.1230x over previous
#include <cuda_runtime.h>
#include <cuda_bf16.h>
#include <cstdint>
#include <cstddef>

// ---------------------------------------------------------------------------
// Problem constants
// ---------------------------------------------------------------------------
constexpr int NB = 4096;
constexpr int ND = 512;
constexpr int NH = 2048;
constexpr int NSTATE = NB * ND;
constexpr int NSTEPS = 20;
constexpr int NCORR  = 3;

// ---------------------------------------------------------------------------
// Scratch (device globals)
// ---------------------------------------------------------------------------
__device__ float g_y[NSTATE];
__device__ float g_acc[NSTATE];
__device__ float g_kk[NSTATE];
__device__ float g_pred[NSTATE];
__device__ float g_base[NSTATE];
__device__ float g_hist[4 * NSTATE];

__device__ __nv_bfloat16 g_pin_hi[NSTATE];      // feval input planes
__device__ __nv_bfloat16 g_pin_lo[NSTATE];
__device__ __nv_bfloat16 g_w1t_hi[(size_t)NH * ND];
__device__ __nv_bfloat16 g_w1t_lo[(size_t)NH * ND];
__device__ __nv_bfloat16 g_w2t_hi[(size_t)ND * NH];
__device__ __nv_bfloat16 g_w2t_lo[(size_t)ND * NH];
__device__ __nv_bfloat16 g_act_hi[(size_t)NB * NH];
__device__ __nv_bfloat16 g_act_lo[(size_t)NB * NH];

// ---------------------------------------------------------------------------
// Helpers
// ---------------------------------------------------------------------------
__device__ __forceinline__ uint32_t smem_u32(const void* p) {
    uint32_t a;
    asm("{ .reg .u64 t; cvta.to.shared.u64 t, %1; cvt.u32.u64 %0, t; }"
        : "=r"(a) : "l"(p));
    return a;
}

__device__ __forceinline__ uint32_t swz(uint32_t o) {
    return o ^ ((o >> 3) & 0x70);
}

__device__ __forceinline__ void cpa16(uint32_t s, const void* g) {
    asm volatile("cp.async.cg.shared.global [%0], [%1], 16;" :: "r"(s), "l"(g));
}
__device__ __forceinline__ void cpa_commit() {
    asm volatile("cp.async.commit_group;");
}

__device__ __forceinline__ void ldmx4(uint32_t r[4], uint32_t addr) {
    asm volatile("ldmatrix.sync.aligned.m8n8.x4.shared.b16 {%0,%1,%2,%3}, [%4];"
                 : "=r"(r[0]), "=r"(r[1]), "=r"(r[2]), "=r"(r[3]) : "r"(addr));
}

__device__ __forceinline__ void mma16816(float d[4], const uint32_t a[4],
                                         uint32_t b0, uint32_t b1) {
    asm volatile(
        "mma.sync.aligned.m16n8k16.row.col.f32.bf16.bf16.f32 "
        "{%0,%1,%2,%3}, {%4,%5,%6,%7}, {%8,%9}, {%0,%1,%2,%3};"
        : "+f"(d[0]), "+f"(d[1]), "+f"(d[2]), "+f"(d[3])
        : "r"(a[0]), "r"(a[1]), "r"(a[2]), "r"(a[3]), "r"(b0), "r"(b1));
}

__device__ __forceinline__ uint32_t pk2(__nv_bfloat16 a, __nv_bfloat16 b) {
    __nv_bfloat162 t = __halves2bfloat162(a, b);
    return *reinterpret_cast<uint32_t*>(&t);
}
__device__ __forceinline__ void split1(float v, __nv_bfloat16& h, __nv_bfloat16& l) {
    h = __float2bfloat16(v);
    l = __float2bfloat16(v - __bfloat162float(h));
}
// split a float4 into packed hi/lo uint2
__device__ __forceinline__ void split4(float4 v, uint2& oh, uint2& ol) {
    __nv_bfloat16 h0, h1, h2, h3, l0, l1, l2, l3;
    split1(v.x, h0, l0); split1(v.y, h1, l1);
    split1(v.z, h2, l2); split1(v.w, h3, l3);
    oh.x = pk2(h0, h1); oh.y = pk2(h2, h3);
    ol.x = pk2(l0, l1); ol.y = pk2(l2, l3);
}

// ---------------------------------------------------------------------------
// Unified bf16x2-split HMMA GEMM, cp.async 3-stage pipeline.
//   C[M,N] = epi(A[M,K] @ BT[N,K]^T + bias)
//   A, B given as bf16 hi/lo planes (row-major, K contiguous).
//   MODE 0: out = tanh -> bf16 hi/lo planes
//   MODE 1: out = alpha*(acc+bias) [+addv] -> fp32 (+ optional hi/lo planes)
// CTA 128x128, BK=64, 8 warps (4x2, each 32x64).
// SMEM/stage: 4 planes x 128 rows x 128B = 64KB; 3 stages = 192KB.
// ---------------------------------------------------------------------------
constexpr int GEMM_SMEM = 3 * 65536;   // 196608

template <int MODE>
__global__ __launch_bounds__(256, 1)
void gemm_cp(const __nv_bfloat16* __restrict__ Ah,
             const __nv_bfloat16* __restrict__ Al,
             const __nv_bfloat16* __restrict__ Bh,
             const __nv_bfloat16* __restrict__ Bl,
             const float* __restrict__ bias,
             float* __restrict__ Cf,
             __nv_bfloat16* __restrict__ Chi,
             __nv_bfloat16* __restrict__ Clo,
             const float* __restrict__ addv, float alpha,
             int N, int K)
{
    extern __shared__ char smem[];
    const uint32_t sbase = smem_u32(smem);
    const int tid = threadIdx.x;
    const int wid = tid >> 5, lane = tid & 31;
    const int wm = wid & 3;
    const int wn = wid >> 2;
    const int bm = blockIdx.y * 128, bn = blockIdx.x * 128;

    // ldmatrix per-lane byte offsets within a 16KB plane
    const uint32_t aoff0 = (uint32_t)(wm * 32 + (lane & 15)) * 128 + ((lane >> 4) * 16);
    const int bg = lane >> 3;
    const uint32_t boff0 = (uint32_t)(wn * 64 + (lane & 7) + ((bg & 2) ? 8 : 0)) * 128
                         + ((bg & 1) * 16);

    // per-thread cp.async mapping: idx = i*256+tid -> row idx>>3, 16B col idx&7
    const int cr = tid >> 3;            // base row (i adds 32 rows each)
    const int cc = (tid & 7) * 8;       // element col offset (8 bf16 = 16B)
    const uint32_t so0 = swz((uint32_t)cr * 128 + (tid & 7) * 16);

    float acc[2][8][4];
    #pragma unroll
    for (int mt = 0; mt < 2; mt++)
        #pragma unroll
        for (int nt = 0; nt < 8; nt++)
            #pragma unroll
            for (int q = 0; q < 4; q++) acc[mt][nt][q] = 0.f;

    const int T = K >> 6;

    auto issue = [&](int c) {
        const int st = c - (c / 3) * 3;
        const uint32_t s = sbase + (uint32_t)st * 65536;
        const int k0 = c << 6;
        #pragma unroll
        for (int i = 0; i < 4; i++) {
            const int r = cr + i * 32;
            const uint32_t so = so0 + (uint32_t)i * 32 * 128;
            const size_t ga = (size_t)(bm + r) * K + k0 + cc;
            const size_t gb = (size_t)(bn + r) * K + k0 + cc;
            cpa16(s + so,          Ah + ga);
            cpa16(s + 16384 + so,  Al + ga);
            cpa16(s + 32768 + so,  Bh + gb);
            cpa16(s + 49152 + so,  Bl + gb);
        }
        cpa_commit();
    };

    auto compute = [&](int st) {
        const uint32_t sa_h = sbase + (uint32_t)st * 65536;
        const uint32_t sa_l = sa_h + 16384;
        const uint32_t sb_h = sa_l + 16384;
        const uint32_t sb_l = sb_h + 16384;
        #pragma unroll
        for (int ks = 0; ks < 4; ks++) {
            const uint32_t kb = ks * 32;
            uint32_t ah[2][4], al2[2][4], bh[4][4], bl[4][4];
            #pragma unroll
            for (int mt = 0; mt < 2; mt++) {
                uint32_t o = aoff0 + (uint32_t)mt * 16 * 128 + kb;
                ldmx4(ah[mt],  sa_h + swz(o));
                ldmx4(al2[mt], sa_l + swz(o));
            }
            #pragma unroll
            for (int np = 0; np < 4; np++) {
                uint32_t o = boff0 + (uint32_t)np * 16 * 128 + kb;
                ldmx4(bh[np], sb_h + swz(o));
                ldmx4(bl[np], sb_l + swz(o));
            }
            #pragma unroll
            for (int mt = 0; mt < 2; mt++)
                #pragma unroll
                for (int nt = 0; nt < 8; nt++) {
                    const int np = nt >> 1, hh = (nt & 1) * 2;
                    mma16816(acc[mt][nt], ah[mt],  bh[np][hh], bh[np][hh + 1]);
                    mma16816(acc[mt][nt], ah[mt],  bl[np][hh], bl[np][hh + 1]);
                    mma16816(acc[mt][nt], al2[mt], bh[np][hh], bh[np][hh + 1]);
                }
        }
    };

    // ---- pipelined mainloop ----
    issue(0);
    issue(1);
    for (int c = 0; c < T; c++) {
        if (c + 1 < T) asm volatile("cp.async.wait_group 1;" ::: "memory");
        else           asm volatile("cp.async.wait_group 0;" ::: "memory");
        __syncthreads();
        if (c + 2 < T) issue(c + 2);
        compute(c - (c / 3) * 3);
    }

    // ---- epilogue from accumulators ----
    const int r0l = lane >> 2, c0l = (lane & 3) * 2;
    #pragma unroll
    for (int mt = 0; mt < 2; mt++) {
        const int rowA = bm + wm * 32 + mt * 16 + r0l;
        #pragma unroll
        for (int nt = 0; nt < 8; nt++) {
            const int col = bn + wn * 64 + nt * 8 + c0l;
            const float2 bb = *(const float2*)(bias + col);
            #pragma unroll
            for (int half = 0; half < 2; half++) {
                const int row = rowA + half * 8;
                float v0 = acc[mt][nt][half * 2 + 0] + bb.x;
                float v1 = acc[mt][nt][half * 2 + 1] + bb.y;
                if (MODE == 0) {
                    v0 = tanhf(v0); v1 = tanhf(v1);
                    __nv_bfloat16 h0, l0, h1, l1;
                    split1(v0, h0, l0); split1(v1, h1, l1);
                    *(uint32_t*)(Chi + (size_t)row * N + col) = pk2(h0, h1);
                    *(uint32_t*)(Clo + (size_t)row * N + col) = pk2(l0, l1);
                } else {
                    v0 *= alpha; v1 *= alpha;
                    if (addv) {
                        float2 a2 = *(const float2*)(addv + (size_t)row * N + col);
                        v0 += a2.x; v1 += a2.y;
                    }
                    *(float2*)(Cf + (size_t)row * N + col) = make_float2(v0, v1);
                    if (Chi) {
                        __nv_bfloat16 h0, l0, h1, l1;
                        split1(v0, h0, l0); split1(v1, h1, l1);
                        *(uint32_t*)(Chi + (size_t)row * N + col) = pk2(h0, h1);
                        *(uint32_t*)(Clo + (size_t)row * N + col) = pk2(l0, l1);
                    }
                }
            }
        }
    }
}

// ---------------------------------------------------------------------------
// Weight transpose + bf16 split: W[K][N] -> T_hi/T_lo[N][K]
// ---------------------------------------------------------------------------
__global__ void k_tsplit(const float* __restrict__ W,
                         __nv_bfloat16* __restrict__ Th,
                         __nv_bfloat16* __restrict__ Tl, int K, int N)
{
    __shared__ float t[32][33];
    const int n0 = blockIdx.x * 32, k0 = blockIdx.y * 32;
    for (int i = threadIdx.y; i < 32; i += 8)
        t[i][threadIdx.x] = W[(size_t)(k0 + i) * N + n0 + threadIdx.x];
    __syncthreads();
    for (int i = threadIdx.y; i < 32; i += 8) {
        float v = t[threadIdx.x][i];
        __nv_bfloat16 h, l;
        split1(v, h, l);
        size_t o = (size_t)(n0 + i) * K + k0 + threadIdx.x;
        Th[o] = h; Tl[o] = l;
    }
}

// ---------------------------------------------------------------------------
// Elementwise kernels (float4 lanes; planes as uint2)
// ---------------------------------------------------------------------------
__global__ void k_split(float4* __restrict__ o, uint2* __restrict__ oh,
                        uint2* __restrict__ ol, const float4* __restrict__ src)
{
    int i = blockIdx.x * 256 + threadIdx.x;
    float4 v = src[i];
    o[i] = v;
    uint2 h2, l2; split4(v, h2, l2);
    oh[i] = h2; ol[i] = l2;
}

__global__ void k_axpy(float4* __restrict__ o, const float4* __restrict__ y,
                       const float4* __restrict__ k, float a)
{
    int i = blockIdx.x * 256 + threadIdx.x;
    float4 yv = y[i], kv = k[i];
    o[i] = make_float4(fmaf(a, kv.x, yv.x), fmaf(a, kv.y, yv.y),
                       fmaf(a, kv.z, yv.z), fmaf(a, kv.w, yv.w));
}

// planes-only: split(y + a*k)
__global__ void k_axpy_sp(uint2* __restrict__ oh, uint2* __restrict__ ol,
                          const float4* __restrict__ y,
                          const float4* __restrict__ k, float a)
{
    int i = blockIdx.x * 256 + threadIdx.x;
    float4 yv = y[i], kv = k[i];
    float4 v = make_float4(fmaf(a, kv.x, yv.x), fmaf(a, kv.y, yv.y),
                           fmaf(a, kv.z, yv.z), fmaf(a, kv.w, yv.w));
    uint2 h2, l2; split4(v, h2, l2);
    oh[i] = h2; ol[i] = l2;
}

__global__ void k_acc(float4* __restrict__ o, const float4* __restrict__ p, float a)
{
    int i = blockIdx.x * 256 + threadIdx.x;
    float4 ov = o[i], pv = p[i];
    o[i] = make_float4(fmaf(a, pv.x, ov.x), fmaf(a, pv.y, ov.y),
                       fmaf(a, pv.z, ov.z), fmaf(a, pv.w, ov.w));
}

// o += a*p, also emit planes of the result
__global__ void k_acc_sp(float4* __restrict__ o, const float4* __restrict__ p,
                         float a, uint2* __restrict__ oh, uint2* __restrict__ ol)
{
    int i = blockIdx.x * 256 + threadIdx.x;
    float4 ov = o[i], pv = p[i];
    float4 v = make_float4(fmaf(a, pv.x, ov.x), fmaf(a, pv.y, ov.y),
                           fmaf(a, pv.z, ov.z), fmaf(a, pv.w, ov.w));
    o[i] = v;
    uint2 h2, l2; split4(v, h2, l2);
    oh[i] = h2; ol[i] = l2;
}

// pred = y + c*(55 h0 - 59 h1 + 37 h2 - 9 h3), fp32 + planes
__global__ void k_pred_sp(float4* __restrict__ o, const float4* __restrict__ y,
                          const float4* __restrict__ h0, const float4* __restrict__ h1,
                          const float4* __restrict__ h2, const float4* __restrict__ h3,
                          float c, uint2* __restrict__ oh, uint2* __restrict__ ol)
{
    int i = blockIdx.x * 256 + threadIdx.x;
    float4 yv = y[i], a = h0[i], b = h1[i], d = h2[i], e = h3[i];
    float4 r;
    r.x = yv.x + c * (55.f * a.x - 59.f * b.x + 37.f * d.x - 9.f * e.x);
    r.y = yv.y + c * (55.f * a.y - 59.f * b.y + 37.f * d.y - 9.f * e.y);
    r.z = yv.z + c * (55.f * a.z - 59.f * b.z + 37.f * d.z - 9.f * e.z);
    r.w = yv.w + c * (55.f * a.w - 59.f * b.w + 37.f * d.w - 9.f * e.w);
    o[i] = r;
    uint2 h2p, l2p; split4(r, h2p, l2p);
    oh[i] = h2p; ol[i] = l2p;
}

__global__ void k_base(float4* __restrict__ o, const float4* __restrict__ y,
                       const float4* __restrict__ h0, const float4* __restrict__ h1,
                       const float4* __restrict__ h2, float c)
{
    int i = blockIdx.x * 256 + threadIdx.x;
    float4 yv = y[i], a = h0[i], b = h1[i], d = h2[i];
    float4 r;
    r.x = yv.x + c * (19.f * a.x - 5.f * b.x + d.x);
    r.y = yv.y + c * (19.f * a.y - 5.f * b.y + d.y);
    r.z = yv.z + c * (19.f * a.z - 5.f * b.z + d.z);
    r.w = yv.w + c * (19.f * a.w - 5.f * b.w + d.w);
    o[i] = r;
}

// ---------------------------------------------------------------------------
// Host orchestration
// ---------------------------------------------------------------------------
extern "C" void kernel_launch(void* const* d_in, const int* in_sizes, int n_in,
                              void* d_out, int out_size)
{
    const float* x  = (const float*)d_in[0];
    const float* W1 = (const float*)d_in[1];
    const float* b1 = (const float*)d_in[2];
    const float* W2 = (const float*)d_in[3];
    const float* b2 = (const float*)d_in[4];
    float* out = (float*)d_out;

    float *y, *acc, *kk, *pred, *base, *histbase;
    __nv_bfloat16 *pinh, *pinl, *w1h, *w1l, *w2h, *w2l, *ah, *al;
    cudaGetSymbolAddress((void**)&y,        g_y);
    cudaGetSymbolAddress((void**)&acc,      g_acc);
    cudaGetSymbolAddress((void**)&kk,       g_kk);
    cudaGetSymbolAddress((void**)&pred,     g_pred);
    cudaGetSymbolAddress((void**)&base,     g_base);
    cudaGetSymbolAddress((void**)&histbase, g_hist);
    cudaGetSymbolAddress((void**)&pinh,     g_pin_hi);
    cudaGetSymbolAddress((void**)&pinl,     g_pin_lo);
    cudaGetSymbolAddress((void**)&w1h,      g_w1t_hi);
    cudaGetSymbolAddress((void**)&w1l,      g_w1t_lo);
    cudaGetSymbolAddress((void**)&w2h,      g_w2t_hi);
    cudaGetSymbolAddress((void**)&w2l,      g_w2t_lo);
    cudaGetSymbolAddress((void**)&ah,       g_act_hi);
    cudaGetSymbolAddress((void**)&al,       g_act_lo);

    cudaFuncSetAttribute(gemm_cp<0>, cudaFuncAttributeMaxDynamicSharedMemorySize, GEMM_SMEM);
    cudaFuncSetAttribute(gemm_cp<1>, cudaFuncAttributeMaxDynamicSharedMemorySize, GEMM_SMEM);

    float* h[4];
    for (int i = 0; i < 4; i++) h[i] = histbase + (size_t)i * NSTATE;

    const float dt = 1.0f / (float)NSTEPS;
    const float c  = dt / 24.0f;

    const dim3 blk(256);
    const dim3 grid1(NH / 128, NB / 128);
    const dim3 grid2(ND / 128, NB / 128);
    const int EG = NSTATE / 4 / 256;

    k_tsplit<<<dim3(NH / 32, ND / 32), dim3(32, 8)>>>(W1, w1h, w1l, ND, NH);
    k_tsplit<<<dim3(ND / 32, NH / 32), dim3(32, 8)>>>(W2, w2h, w2l, NH, ND);

    // f(pin planes) -> dstF (fp32) [+ optional planes dsth/dstl]
    auto feval = [&](float* dstF, __nv_bfloat16* dsth, __nv_bfloat16* dstl,
                     float alpha, const float* addv) {
        gemm_cp<0><<<grid1, blk, GEMM_SMEM>>>(pinh, pinl, w1h, w1l, b1,
                                              nullptr, ah, al, nullptr, 1.f, NH, ND);
        gemm_cp<1><<<grid2, blk, GEMM_SMEM>>>(ah, al, w2h, w2l, b2,
                                              dstF, dsth, dstl, addv, alpha, ND, NH);
    };

    // y = x (fp32 + planes)
    k_split<<<EG, blk>>>((float4*)y, (uint2*)pinh, (uint2*)pinl, (const float4*)x);

    // ---- bootstrap: f(y0) -> h[3] ----
    feval(h[3], nullptr, nullptr, 1.f, nullptr);

    // ---- 3 RK4 steps; k1 reused from most recent hist entry ----
    for (int s = 0; s < 3; s++) {
        float* k1 = h[3 - s];
        k_axpy   <<<EG, blk>>>((float4*)acc, (const float4*)y, (const float4*)k1, dt / 6.f);
        k_axpy_sp<<<EG, blk>>>((uint2*)pinh, (uint2*)pinl,
                               (const float4*)y, (const float4*)k1, 0.5f * dt);
        feval(kk, nullptr, nullptr, 1.f, nullptr);                           // k2
        k_acc    <<<EG, blk>>>((float4*)acc, (const float4*)kk, dt / 3.f);
        k_axpy_sp<<<EG, blk>>>((uint2*)pinh, (uint2*)pinl,
                               (const float4*)y, (const float4*)kk, 0.5f * dt);
        feval(kk, nullptr, nullptr, 1.f, nullptr);                           // k3
        k_acc    <<<EG, blk>>>((float4*)acc, (const float4*)kk, dt / 3.f);
        k_axpy_sp<<<EG, blk>>>((uint2*)pinh, (uint2*)pinl,
                               (const float4*)y, (const float4*)kk, dt);
        feval(kk, nullptr, nullptr, 1.f, nullptr);                           // k4
        k_acc_sp <<<EG, blk>>>((float4*)acc, (const float4*)kk, dt / 6.f,
                               (uint2*)pinh, (uint2*)pinl);
        { float* t = y; y = acc; acc = t; }
        feval(h[2 - s], nullptr, nullptr, 1.f, nullptr);     // f(y_new) = next k1
    }

    // ---- 17 ABM4 predictor-corrector steps ----
    const int NABM = NSTEPS - 3;
    for (int i = 0; i < NABM; i++) {
        k_pred_sp<<<EG, blk>>>((float4*)pred, (const float4*)y,
                               (const float4*)h[0], (const float4*)h[1],
                               (const float4*)h[2], (const float4*)h[3], c,
                               (uint2*)pinh, (uint2*)pinl);
        k_base<<<EG, blk>>>((float4*)base, (const float4*)y,
                            (const float4*)h[0], (const float4*)h[1],
                            (const float4*)h[2], c);
        for (int j = 0; j < NCORR; j++) {
            const bool last = (i == NABM - 1) && (j == NCORR - 1);
            if (last) feval(out,  nullptr, nullptr, 9.f * c, base);
            else      feval(pred, pinh,    pinl,    9.f * c, base);
        }
        if (i < NABM - 1) {
            feval(h[3], nullptr, nullptr, 1.f, nullptr);     // f(pred)
            float* t = h[3]; h[3] = h[2]; h[2] = h[1]; h[1] = h[0]; h[0] = t;
            float* t2 = y; y = pred; pred = t2;
        }
    }
}

// round 7
// speedup vs baseline: 3.1060x; 1.0205x over previous
#include <cuda_runtime.h>
#include <cuda_bf16.h>
#include <cstdint>
#include <cstddef>

// ---------------------------------------------------------------------------
// Problem constants
// ---------------------------------------------------------------------------
constexpr int NB = 4096;
constexpr int ND = 512;
constexpr int NH = 2048;
constexpr int NSTATE = NB * ND;
constexpr int NSTEPS = 20;
constexpr int NCORR  = 3;

// ---------------------------------------------------------------------------
// Scratch (device globals)
// ---------------------------------------------------------------------------
__device__ float g_y[NSTATE];
__device__ float g_acc[NSTATE];
__device__ float g_kk[NSTATE];
__device__ float g_pred[NSTATE];
__device__ float g_base[NSTATE];
__device__ float g_hist[4 * NSTATE];
__device__ float g_part[2 * NSTATE];            // split-K partials for gemm2

__device__ __nv_bfloat16 g_pin_hi[NSTATE];      // feval input planes
__device__ __nv_bfloat16 g_pin_lo[NSTATE];
__device__ __nv_bfloat16 g_w1t_hi[(size_t)NH * ND];
__device__ __nv_bfloat16 g_w1t_lo[(size_t)NH * ND];
__device__ __nv_bfloat16 g_w2t_hi[(size_t)ND * NH];
__device__ __nv_bfloat16 g_w2t_lo[(size_t)ND * NH];
__device__ __nv_bfloat16 g_act_hi[(size_t)NB * NH];
__device__ __nv_bfloat16 g_act_lo[(size_t)NB * NH];

// ---------------------------------------------------------------------------
// Helpers
// ---------------------------------------------------------------------------
__device__ __forceinline__ uint32_t smem_u32(const void* p) {
    uint32_t a;
    asm("{ .reg .u64 t; cvta.to.shared.u64 t, %1; cvt.u32.u64 %0, t; }"
        : "=r"(a) : "l"(p));
    return a;
}

__device__ __forceinline__ uint32_t swz(uint32_t o) {
    return o ^ ((o >> 3) & 0x70);
}

__device__ __forceinline__ void cpa16(uint32_t s, const void* g) {
    asm volatile("cp.async.cg.shared.global [%0], [%1], 16;" :: "r"(s), "l"(g));
}

__device__ __forceinline__ void ldmx4(uint32_t r[4], uint32_t addr) {
    asm volatile("ldmatrix.sync.aligned.m8n8.x4.shared.b16 {%0,%1,%2,%3}, [%4];"
                 : "=r"(r[0]), "=r"(r[1]), "=r"(r[2]), "=r"(r[3]) : "r"(addr));
}

__device__ __forceinline__ void mma16816(float d[4], const uint32_t a[4],
                                         uint32_t b0, uint32_t b1) {
    asm volatile(
        "mma.sync.aligned.m16n8k16.row.col.f32.bf16.bf16.f32 "
        "{%0,%1,%2,%3}, {%4,%5,%6,%7}, {%8,%9}, {%0,%1,%2,%3};"
        : "+f"(d[0]), "+f"(d[1]), "+f"(d[2]), "+f"(d[3])
        : "r"(a[0]), "r"(a[1]), "r"(a[2]), "r"(a[3]), "r"(b0), "r"(b1));
}

__device__ __forceinline__ uint32_t pk2(__nv_bfloat16 a, __nv_bfloat16 b) {
    __nv_bfloat162 t = __halves2bfloat162(a, b);
    return *reinterpret_cast<uint32_t*>(&t);
}
__device__ __forceinline__ void split1(float v, __nv_bfloat16& h, __nv_bfloat16& l) {
    h = __float2bfloat16(v);
    l = __float2bfloat16(v - __bfloat162float(h));
}
__device__ __forceinline__ void split4(float4 v, uint2& oh, uint2& ol) {
    __nv_bfloat16 h0, h1, h2, h3, l0, l1, l2, l3;
    split1(v.x, h0, l0); split1(v.y, h1, l1);
    split1(v.z, h2, l2); split1(v.w, h3, l3);
    oh.x = pk2(h0, h1); oh.y = pk2(h2, h3);
    ol.x = pk2(l0, l1); ol.y = pk2(l2, l3);
}

// ---------------------------------------------------------------------------
// bf16x2-split HMMA GEMM, 2-stage cp.async, CTA tile 256x128, warp tile 64x64.
//   EPI 0: C = tanh(acc + bias) -> bf16 hi/lo planes (ld N)
//   EPI 1: partial fp32 store (split-K slice via blockIdx.z), no bias
// SMEM/stage: A 2x32KB + B 2x16KB = 96KB; 2 stages = 192KB.
// ---------------------------------------------------------------------------
constexpr int GEMM_SMEM = 2 * 98304;   // 196608

template <int EPI>
__global__ __launch_bounds__(256, 1)
void gemm_cp(const __nv_bfloat16* __restrict__ Ah,
             const __nv_bfloat16* __restrict__ Al, int lda,
             const __nv_bfloat16* __restrict__ Bh,
             const __nv_bfloat16* __restrict__ Bl, int ldb,
             int nchunks, int kslice,
             const float* __restrict__ bias,
             __nv_bfloat16* __restrict__ Chi,
             __nv_bfloat16* __restrict__ Clo,
             float* __restrict__ Cp,
             int N)
{
    extern __shared__ char smem[];
    const uint32_t sbase = smem_u32(smem);
    const int tid = threadIdx.x;
    const int wid = tid >> 5, lane = tid & 31;
    const int wm = wid & 3;            // 4 row-blocks of 64
    const int wn = wid >> 2;           // 2 col-blocks of 64
    const int bm = blockIdx.y * 256, bn = blockIdx.x * 128;
    const int koff = blockIdx.z * kslice;
    if (EPI == 1) Cp += (size_t)blockIdx.z * NSTATE;

    // cp.async per-thread mapping: idx = i*256+tid -> row idx>>3, 16B-col idx&7
    const int cr = tid >> 3;
    const int cq = tid & 7;
    const uint32_t so0 = swz((uint32_t)cr * 128 + cq * 16);

    const int bg = lane >> 3;
    const uint32_t boffl = (uint32_t)((lane & 7) + ((bg & 2) ? 8 : 0)) * 128
                         + (bg & 1) * 16;
    const uint32_t aoffl = (uint32_t)(lane & 15) * 128 + (lane >> 4) * 16;

    float acc[4][8][4];
    #pragma unroll
    for (int mt = 0; mt < 4; mt++)
        #pragma unroll
        for (int nt = 0; nt < 8; nt++)
            #pragma unroll
            for (int q = 0; q < 4; q++) acc[mt][nt][q] = 0.f;

    auto issue = [&](int c) {
        const uint32_t s = sbase + (uint32_t)(c & 1) * 98304;
        const int k0 = koff + (c << 6);
        #pragma unroll
        for (int i = 0; i < 8; i++) {            // A: 256 rows
            const int r = cr + i * 32;
            const uint32_t so = so0 + (uint32_t)i * 32 * 128;
            const size_t ga = (size_t)(bm + r) * lda + k0 + cq * 8;
            cpa16(s + so,         Ah + ga);
            cpa16(s + 32768 + so, Al + ga);
        }
        #pragma unroll
        for (int i = 0; i < 4; i++) {            // B: 128 rows
            const int r = cr + i * 32;
            const uint32_t so = so0 + (uint32_t)i * 32 * 128;
            const size_t gb = (size_t)(bn + r) * ldb + k0 + cq * 8;
            cpa16(s + 65536 + so, Bh + gb);
            cpa16(s + 81920 + so, Bl + gb);
        }
        asm volatile("cp.async.commit_group;");
    };

    auto compute = [&](int st) {
        const uint32_t sa_h = sbase + (uint32_t)st * 98304;
        const uint32_t sa_l = sa_h + 32768;
        const uint32_t sb_h = sa_h + 65536;
        const uint32_t sb_l = sa_h + 81920;
        #pragma unroll
        for (int ks = 0; ks < 4; ks++) {
            const uint32_t kb = ks * 32;
            uint32_t ah[4][4], al2[4][4];
            #pragma unroll
            for (int mt = 0; mt < 4; mt++) {
                const uint32_t o = aoffl + (uint32_t)(wm * 64 + mt * 16) * 128 + kb;
                ldmx4(ah[mt],  sa_h + swz(o));
                ldmx4(al2[mt], sa_l + swz(o));
            }
            #pragma unroll
            for (int np = 0; np < 4; np++) {
                uint32_t bh[4], bl[4];
                const uint32_t o = boffl + (uint32_t)(wn * 64 + np * 16) * 128 + kb;
                ldmx4(bh, sb_h + swz(o));
                ldmx4(bl, sb_l + swz(o));
                #pragma unroll
                for (int mt = 0; mt < 4; mt++)
                    #pragma unroll
                    for (int h2 = 0; h2 < 2; h2++) {
                        const int nt = np * 2 + h2;
                        mma16816(acc[mt][nt], ah[mt],  bh[h2 * 2], bh[h2 * 2 + 1]);
                        mma16816(acc[mt][nt], ah[mt],  bl[h2 * 2], bl[h2 * 2 + 1]);
                        mma16816(acc[mt][nt], al2[mt], bh[h2 * 2], bh[h2 * 2 + 1]);
                    }
            }
        }
    };

    issue(0);
    for (int c = 0; c < nchunks; c++) {
        asm volatile("cp.async.wait_group 0;" ::: "memory");
        __syncthreads();
        if (c + 1 < nchunks) issue(c + 1);
        compute(c & 1);
    }

    // ---- epilogue ----
    const int r0l = lane >> 2, c0l = (lane & 3) * 2;
    #pragma unroll
    for (int mt = 0; mt < 4; mt++) {
        const int rowA = bm + wm * 64 + mt * 16 + r0l;
        #pragma unroll
        for (int nt = 0; nt < 8; nt++) {
            const int col = bn + wn * 64 + nt * 8 + c0l;
            #pragma unroll
            for (int half = 0; half < 2; half++) {
                const int row = rowA + half * 8;
                float v0 = acc[mt][nt][half * 2 + 0];
                float v1 = acc[mt][nt][half * 2 + 1];
                if (EPI == 0) {
                    const float2 bb = *(const float2*)(bias + col);
                    v0 = tanhf(v0 + bb.x); v1 = tanhf(v1 + bb.y);
                    __nv_bfloat16 h0, l0, h1, l1;
                    split1(v0, h0, l0); split1(v1, h1, l1);
                    *(uint32_t*)(Chi + (size_t)row * N + col) = pk2(h0, h1);
                    *(uint32_t*)(Clo + (size_t)row * N + col) = pk2(l0, l1);
                } else {
                    *(float2*)(Cp + (size_t)row * N + col) = make_float2(v0, v1);
                }
            }
        }
    }
}

// ---------------------------------------------------------------------------
// Weight transpose + bf16 split: W[K][N] -> T_hi/T_lo[N][K]
// ---------------------------------------------------------------------------
__global__ void k_tsplit(const float* __restrict__ W,
                         __nv_bfloat16* __restrict__ Th,
                         __nv_bfloat16* __restrict__ Tl, int K, int N)
{
    __shared__ float t[32][33];
    const int n0 = blockIdx.x * 32, k0 = blockIdx.y * 32;
    for (int i = threadIdx.y; i < 32; i += 8)
        t[i][threadIdx.x] = W[(size_t)(k0 + i) * N + n0 + threadIdx.x];
    __syncthreads();
    for (int i = threadIdx.y; i < 32; i += 8) {
        float v = t[threadIdx.x][i];
        __nv_bfloat16 h, l;
        split1(v, h, l);
        size_t o = (size_t)(n0 + i) * K + k0 + threadIdx.x;
        Th[o] = h; Tl[o] = l;
    }
}

// ---------------------------------------------------------------------------
// Combine: dst = alpha*(p0+p1+bias) [+ addv], optional planes of dst
// float4 over NSTATE; bias is [512] broadcast: col4 = i & 127
// ---------------------------------------------------------------------------
__global__ void k_comb(float4* __restrict__ dst,
                       const float4* __restrict__ p0, const float4* __restrict__ p1,
                       const float4* __restrict__ bias4,
                       const float4* __restrict__ addv, float alpha,
                       uint2* __restrict__ oh, uint2* __restrict__ ol)
{
    int i = blockIdx.x * 256 + threadIdx.x;
    float4 a = p0[i], b = p1[i], bb = bias4[i & 127];
    float4 v;
    v.x = alpha * (a.x + b.x + bb.x);
    v.y = alpha * (a.y + b.y + bb.y);
    v.z = alpha * (a.z + b.z + bb.z);
    v.w = alpha * (a.w + b.w + bb.w);
    if (addv) {
        float4 av = addv[i];
        v.x += av.x; v.y += av.y; v.z += av.z; v.w += av.w;
    }
    dst[i] = v;
    if (oh) {
        uint2 h2, l2; split4(v, h2, l2);
        oh[i] = h2; ol[i] = l2;
    }
}

// ---------------------------------------------------------------------------
// Elementwise kernels
// ---------------------------------------------------------------------------
__global__ void k_split(float4* __restrict__ o, uint2* __restrict__ oh,
                        uint2* __restrict__ ol, const float4* __restrict__ src)
{
    int i = blockIdx.x * 256 + threadIdx.x;
    float4 v = src[i];
    o[i] = v;
    uint2 h2, l2; split4(v, h2, l2);
    oh[i] = h2; ol[i] = l2;
}

__global__ void k_axpy(float4* __restrict__ o, const float4* __restrict__ y,
                       const float4* __restrict__ k, float a)
{
    int i = blockIdx.x * 256 + threadIdx.x;
    float4 yv = y[i], kv = k[i];
    o[i] = make_float4(fmaf(a, kv.x, yv.x), fmaf(a, kv.y, yv.y),
                       fmaf(a, kv.z, yv.z), fmaf(a, kv.w, yv.w));
}

__global__ void k_axpy_sp(uint2* __restrict__ oh, uint2* __restrict__ ol,
                          const float4* __restrict__ y,
                          const float4* __restrict__ k, float a)
{
    int i = blockIdx.x * 256 + threadIdx.x;
    float4 yv = y[i], kv = k[i];
    float4 v = make_float4(fmaf(a, kv.x, yv.x), fmaf(a, kv.y, yv.y),
                           fmaf(a, kv.z, yv.z), fmaf(a, kv.w, yv.w));
    uint2 h2, l2; split4(v, h2, l2);
    oh[i] = h2; ol[i] = l2;
}

__global__ void k_acc(float4* __restrict__ o, const float4* __restrict__ p, float a)
{
    int i = blockIdx.x * 256 + threadIdx.x;
    float4 ov = o[i], pv = p[i];
    o[i] = make_float4(fmaf(a, pv.x, ov.x), fmaf(a, pv.y, ov.y),
                       fmaf(a, pv.z, ov.z), fmaf(a, pv.w, ov.w));
}

__global__ void k_acc_sp(float4* __restrict__ o, const float4* __restrict__ p,
                         float a, uint2* __restrict__ oh, uint2* __restrict__ ol)
{
    int i = blockIdx.x * 256 + threadIdx.x;
    float4 ov = o[i], pv = p[i];
    float4 v = make_float4(fmaf(a, pv.x, ov.x), fmaf(a, pv.y, ov.y),
                           fmaf(a, pv.z, ov.z), fmaf(a, pv.w, ov.w));
    o[i] = v;
    uint2 h2, l2; split4(v, h2, l2);
    oh[i] = h2; ol[i] = l2;
}

__global__ void k_pred_sp(float4* __restrict__ o, const float4* __restrict__ y,
                          const float4* __restrict__ h0, const float4* __restrict__ h1,
                          const float4* __restrict__ h2, const float4* __restrict__ h3,
                          float c, uint2* __restrict__ oh, uint2* __restrict__ ol)
{
    int i = blockIdx.x * 256 + threadIdx.x;
    float4 yv = y[i], a = h0[i], b = h1[i], d = h2[i], e = h3[i];
    float4 r;
    r.x = yv.x + c * (55.f * a.x - 59.f * b.x + 37.f * d.x - 9.f * e.x);
    r.y = yv.y + c * (55.f * a.y - 59.f * b.y + 37.f * d.y - 9.f * e.y);
    r.z = yv.z + c * (55.f * a.z - 59.f * b.z + 37.f * d.z - 9.f * e.z);
    r.w = yv.w + c * (55.f * a.w - 59.f * b.w + 37.f * d.w - 9.f * e.w);
    o[i] = r;
    uint2 h2p, l2p; split4(r, h2p, l2p);
    oh[i] = h2p; ol[i] = l2p;
}

__global__ void k_base(float4* __restrict__ o, const float4* __restrict__ y,
                       const float4* __restrict__ h0, const float4* __restrict__ h1,
                       const float4* __restrict__ h2, float c)
{
    int i = blockIdx.x * 256 + threadIdx.x;
    float4 yv = y[i], a = h0[i], b = h1[i], d = h2[i];
    float4 r;
    r.x = yv.x + c * (19.f * a.x - 5.f * b.x + d.x);
    r.y = yv.y + c * (19.f * a.y - 5.f * b.y + d.y);
    r.z = yv.z + c * (19.f * a.z - 5.f * b.z + d.z);
    r.w = yv.w + c * (19.f * a.w - 5.f * b.w + d.w);
    o[i] = r;
}

// ---------------------------------------------------------------------------
// Host orchestration
// ---------------------------------------------------------------------------
extern "C" void kernel_launch(void* const* d_in, const int* in_sizes, int n_in,
                              void* d_out, int out_size)
{
    const float* x  = (const float*)d_in[0];
    const float* W1 = (const float*)d_in[1];
    const float* b1 = (const float*)d_in[2];
    const float* W2 = (const float*)d_in[3];
    const float* b2 = (const float*)d_in[4];
    float* out = (float*)d_out;

    float *y, *acc, *kk, *pred, *base, *histbase, *part;
    __nv_bfloat16 *pinh, *pinl, *w1h, *w1l, *w2h, *w2l, *ah, *al;
    cudaGetSymbolAddress((void**)&y,        g_y);
    cudaGetSymbolAddress((void**)&acc,      g_acc);
    cudaGetSymbolAddress((void**)&kk,       g_kk);
    cudaGetSymbolAddress((void**)&pred,     g_pred);
    cudaGetSymbolAddress((void**)&base,     g_base);
    cudaGetSymbolAddress((void**)&histbase, g_hist);
    cudaGetSymbolAddress((void**)&part,     g_part);
    cudaGetSymbolAddress((void**)&pinh,     g_pin_hi);
    cudaGetSymbolAddress((void**)&pinl,     g_pin_lo);
    cudaGetSymbolAddress((void**)&w1h,      g_w1t_hi);
    cudaGetSymbolAddress((void**)&w1l,      g_w1t_lo);
    cudaGetSymbolAddress((void**)&w2h,      g_w2t_hi);
    cudaGetSymbolAddress((void**)&w2l,      g_w2t_lo);
    cudaGetSymbolAddress((void**)&ah,       g_act_hi);
    cudaGetSymbolAddress((void**)&al,       g_act_lo);

    cudaFuncSetAttribute(gemm_cp<0>, cudaFuncAttributeMaxDynamicSharedMemorySize, GEMM_SMEM);
    cudaFuncSetAttribute(gemm_cp<1>, cudaFuncAttributeMaxDynamicSharedMemorySize, GEMM_SMEM);

    float* h[4];
    for (int i = 0; i < 4; i++) h[i] = histbase + (size_t)i * NSTATE;

    const float dt = 1.0f / (float)NSTEPS;
    const float c  = dt / 24.0f;

    const dim3 blk(256);
    const dim3 grid1(NH / 128, NB / 256);        // 16 x 16
    const dim3 grid2(ND / 128, NB / 256, 2);     // 4 x 16 x 2 (split-K)
    const int EG = NSTATE / 4 / 256;

    k_tsplit<<<dim3(NH / 32, ND / 32), dim3(32, 8)>>>(W1, w1h, w1l, ND, NH);
    k_tsplit<<<dim3(ND / 32, NH / 32), dim3(32, 8)>>>(W2, w2h, w2l, NH, ND);

    // f(pin planes) -> combine into dstF (+ optional planes), via split-K partials
    auto feval = [&](float* dstF, __nv_bfloat16* dsth, __nv_bfloat16* dstl,
                     float alpha, const float* addv) {
        gemm_cp<0><<<grid1, blk, GEMM_SMEM>>>(pinh, pinl, ND, w1h, w1l, ND,
                                              ND / 64, 0, b1, ah, al, nullptr, NH);
        gemm_cp<1><<<grid2, blk, GEMM_SMEM>>>(ah, al, NH, w2h, w2l, NH,
                                              (NH / 2) / 64, NH / 2, nullptr,
                                              nullptr, nullptr, part, ND);
        k_comb<<<EG, blk>>>((float4*)dstF, (const float4*)part,
                            (const float4*)(part + NSTATE), (const float4*)b2,
                            (const float4*)addv, alpha, (uint2*)dsth, (uint2*)dstl);
    };

    // y = x (fp32 + planes)
    k_split<<<EG, blk>>>((float4*)y, (uint2*)pinh, (uint2*)pinl, (const float4*)x);

    // ---- bootstrap: f(y0) -> h[3] ----
    feval(h[3], nullptr, nullptr, 1.f, nullptr);

    // ---- 3 RK4 steps; k1 reused from most recent hist entry ----
    for (int s = 0; s < 3; s++) {
        float* k1 = h[3 - s];
        k_axpy   <<<EG, blk>>>((float4*)acc, (const float4*)y, (const float4*)k1, dt / 6.f);
        k_axpy_sp<<<EG, blk>>>((uint2*)pinh, (uint2*)pinl,
                               (const float4*)y, (const float4*)k1, 0.5f * dt);
        feval(kk, nullptr, nullptr, 1.f, nullptr);                           // k2
        k_acc    <<<EG, blk>>>((float4*)acc, (const float4*)kk, dt / 3.f);
        k_axpy_sp<<<EG, blk>>>((uint2*)pinh, (uint2*)pinl,
                               (const float4*)y, (const float4*)kk, 0.5f * dt);
        feval(kk, nullptr, nullptr, 1.f, nullptr);                           // k3
        k_acc    <<<EG, blk>>>((float4*)acc, (const float4*)kk, dt / 3.f);
        k_axpy_sp<<<EG, blk>>>((uint2*)pinh, (uint2*)pinl,
                               (const float4*)y, (const float4*)kk, dt);
        feval(kk, nullptr, nullptr, 1.f, nullptr);                           // k4
        k_acc_sp <<<EG, blk>>>((float4*)acc, (const float4*)kk, dt / 6.f,
                               (uint2*)pinh, (uint2*)pinl);
        { float* t = y; y = acc; acc = t; }
        feval(h[2 - s], nullptr, nullptr, 1.f, nullptr);     // f(y_new) = next k1
    }

    // ---- 17 ABM4 predictor-corrector steps ----
    const int NABM = NSTEPS - 3;
    for (int i = 0; i < NABM; i++) {
        k_pred_sp<<<EG, blk>>>((float4*)pred, (const float4*)y,
                               (const float4*)h[0], (const float4*)h[1],
                               (const float4*)h[2], (const float4*)h[3], c,
                               (uint2*)pinh, (uint2*)pinl);
        k_base<<<EG, blk>>>((float4*)base, (const float4*)y,
                            (const float4*)h[0], (const float4*)h[1],
                            (const float4*)h[2], c);
        for (int j = 0; j < NCORR; j++) {
            const bool last = (i == NABM - 1) && (j == NCORR - 1);
            if (last) feval(out,  nullptr, nullptr, 9.f * c, base);
            else      feval(pred, pinh,    pinl,    9.f * c, base);
        }
        if (i < NABM - 1) {
            feval(h[3], nullptr, nullptr, 1.f, nullptr);     // f(pred)
            float* t = h[3]; h[3] = h[2]; h[2] = h[1]; h[1] = h[0]; h[0] = t;
            float* t2 = y; y = pred; pred = t2;
        }
    }
}

// round 9
// speedup vs baseline: 3.1063x; 1.0001x over previous
#include <cuda_runtime.h>
#include <cuda_bf16.h>
#include <cstdint>
#include <cstddef>

// ---------------------------------------------------------------------------
// Problem constants
// ---------------------------------------------------------------------------
constexpr int NB = 4096;
constexpr int ND = 512;
constexpr int NH = 2048;
constexpr int NSTATE = NB * ND;
constexpr int NSTEPS = 20;
constexpr int NCORR  = 3;

// ---------------------------------------------------------------------------
// Scratch (device globals)
// ---------------------------------------------------------------------------
__device__ float g_y[NSTATE];
__device__ float g_acc[NSTATE];
__device__ float g_kk[NSTATE];
__device__ float g_pred[NSTATE];
__device__ float g_base[NSTATE];
__device__ float g_hist[4 * NSTATE];
__device__ float g_part[2 * NSTATE];            // split-K partials for gemm2

__device__ __nv_bfloat16 g_pin_hi[NSTATE];      // feval input planes
__device__ __nv_bfloat16 g_pin_lo[NSTATE];
__device__ __nv_bfloat16 g_w1t_hi[(size_t)NH * ND];
__device__ __nv_bfloat16 g_w1t_lo[(size_t)NH * ND];
__device__ __nv_bfloat16 g_w2t_hi[(size_t)ND * NH];
__device__ __nv_bfloat16 g_w2t_lo[(size_t)ND * NH];
__device__ __nv_bfloat16 g_act_hi[(size_t)NB * NH];
__device__ __nv_bfloat16 g_act_lo[(size_t)NB * NH];

// ---------------------------------------------------------------------------
// Helpers
// ---------------------------------------------------------------------------
__device__ __forceinline__ uint32_t smem_u32(const void* p) {
    uint32_t a;
    asm("{ .reg .u64 t; cvta.to.shared.u64 t, %1; cvt.u32.u64 %0, t; }"
        : "=r"(a) : "l"(p));
    return a;
}

__device__ __forceinline__ uint32_t swz(uint32_t o) {
    return o ^ ((o >> 3) & 0x70);
}

__device__ __forceinline__ void cpa16(uint32_t s, const void* g) {
    asm volatile("cp.async.cg.shared.global [%0], [%1], 16;" :: "r"(s), "l"(g));
}

__device__ __forceinline__ void ldmx4(uint32_t r[4], uint32_t addr) {
    asm volatile("ldmatrix.sync.aligned.m8n8.x4.shared.b16 {%0,%1,%2,%3}, [%4];"
                 : "=r"(r[0]), "=r"(r[1]), "=r"(r[2]), "=r"(r[3]) : "r"(addr));
}

__device__ __forceinline__ void mma16816(float d[4], const uint32_t a[4],
                                         uint32_t b0, uint32_t b1) {
    asm volatile(
        "mma.sync.aligned.m16n8k16.row.col.f32.bf16.bf16.f32 "
        "{%0,%1,%2,%3}, {%4,%5,%6,%7}, {%8,%9}, {%0,%1,%2,%3};"
        : "+f"(d[0]), "+f"(d[1]), "+f"(d[2]), "+f"(d[3])
        : "r"(a[0]), "r"(a[1]), "r"(a[2]), "r"(a[3]), "r"(b0), "r"(b1));
}

__device__ __forceinline__ uint32_t pk2(__nv_bfloat16 a, __nv_bfloat16 b) {
    __nv_bfloat162 t = __halves2bfloat162(a, b);
    return *reinterpret_cast<uint32_t*>(&t);
}
__device__ __forceinline__ void split1(float v, __nv_bfloat16& h, __nv_bfloat16& l) {
    h = __float2bfloat16(v);
    l = __float2bfloat16(v - __bfloat162float(h));
}
__device__ __forceinline__ void split4(float4 v, uint2& oh, uint2& ol) {
    __nv_bfloat16 h0, h1, h2, h3, l0, l1, l2, l3;
    split1(v.x, h0, l0); split1(v.y, h1, l1);
    split1(v.z, h2, l2); split1(v.w, h3, l3);
    oh.x = pk2(h0, h1); oh.y = pk2(h2, h3);
    ol.x = pk2(l0, l1); ol.y = pk2(l2, l3);
}

// ---------------------------------------------------------------------------
// bf16x2-split HMMA GEMM, 2-stage cp.async, CTA tile 256x128, warp tile 64x64.
// Product-major MMA ordering: same-accumulator MMAs are 32 instructions apart,
// converting accumulator RAW-latency stalls into throughput-limited issue.
//   EPI 0: C = tanh(acc + bias) -> bf16 hi/lo planes (ld N)
//   EPI 1: partial fp32 store (split-K slice via blockIdx.z), no bias
// SMEM/stage: A 2x32KB + B 2x16KB = 96KB; 2 stages = 192KB.
// ---------------------------------------------------------------------------
constexpr int GEMM_SMEM = 2 * 98304;   // 196608

template <int EPI>
__global__ __launch_bounds__(256, 1)
void gemm_cp(const __nv_bfloat16* __restrict__ Ah,
             const __nv_bfloat16* __restrict__ Al, int lda,
             const __nv_bfloat16* __restrict__ Bh,
             const __nv_bfloat16* __restrict__ Bl, int ldb,
             int nchunks, int kslice,
             const float* __restrict__ bias,
             __nv_bfloat16* __restrict__ Chi,
             __nv_bfloat16* __restrict__ Clo,
             float* __restrict__ Cp,
             int N)
{
    extern __shared__ char smem[];
    const uint32_t sbase = smem_u32(smem);
    const int tid = threadIdx.x;
    const int wid = tid >> 5, lane = tid & 31;
    const int wm = wid & 3;            // 4 row-blocks of 64
    const int wn = wid >> 2;           // 2 col-blocks of 64
    const int bm = blockIdx.y * 256, bn = blockIdx.x * 128;
    const int koff = blockIdx.z * kslice;
    if (EPI == 1) Cp += (size_t)blockIdx.z * NSTATE;

    // cp.async per-thread mapping
    const int cr = tid >> 3;
    const int cq = tid & 7;
    const uint32_t so0 = swz((uint32_t)cr * 128 + cq * 16);

    const int bg = lane >> 3;
    const uint32_t boffl = (uint32_t)((lane & 7) + ((bg & 2) ? 8 : 0)) * 128
                         + (bg & 1) * 16;
    const uint32_t aoffl = (uint32_t)(lane & 15) * 128 + (lane >> 4) * 16;

    float acc[4][8][4];
    #pragma unroll
    for (int mt = 0; mt < 4; mt++)
        #pragma unroll
        for (int nt = 0; nt < 8; nt++)
            #pragma unroll
            for (int q = 0; q < 4; q++) acc[mt][nt][q] = 0.f;

    auto issue = [&](int c) {
        const uint32_t s = sbase + (uint32_t)(c & 1) * 98304;
        const int k0 = koff + (c << 6);
        #pragma unroll
        for (int i = 0; i < 8; i++) {            // A: 256 rows
            const int r = cr + i * 32;
            const uint32_t so = so0 + (uint32_t)i * 32 * 128;
            const size_t ga = (size_t)(bm + r) * lda + k0 + cq * 8;
            cpa16(s + so,         Ah + ga);
            cpa16(s + 32768 + so, Al + ga);
        }
        #pragma unroll
        for (int i = 0; i < 4; i++) {            // B: 128 rows
            const int r = cr + i * 32;
            const uint32_t so = so0 + (uint32_t)i * 32 * 128;
            const size_t gb = (size_t)(bn + r) * ldb + k0 + cq * 8;
            cpa16(s + 65536 + so, Bh + gb);
            cpa16(s + 81920 + so, Bl + gb);
        }
        asm volatile("cp.async.commit_group;");
    };

    auto compute = [&](int st) {
        const uint32_t sa_h = sbase + (uint32_t)st * 98304;
        const uint32_t sa_l = sa_h + 32768;
        const uint32_t sb_h = sa_h + 65536;
        const uint32_t sb_l = sa_h + 81920;
        #pragma unroll
        for (int ks = 0; ks < 4; ks++) {
            const uint32_t kb = ks * 32;
            uint32_t ah[4][4], al2[4][4], bh[4][4], bl[4][4];
            // ---- load ALL fragments for this k-slice ----
            #pragma unroll
            for (int mt = 0; mt < 4; mt++) {
                const uint32_t o = aoffl + (uint32_t)(wm * 64 + mt * 16) * 128 + kb;
                ldmx4(ah[mt],  sa_h + swz(o));
                ldmx4(al2[mt], sa_l + swz(o));
            }
            #pragma unroll
            for (int np = 0; np < 4; np++) {
                const uint32_t o = boffl + (uint32_t)(wn * 64 + np * 16) * 128 + kb;
                ldmx4(bh[np], sb_h + swz(o));
                ldmx4(bl[np], sb_l + swz(o));
            }
            // ---- product-major MMA streams (same-acc distance = 32) ----
            #pragma unroll
            for (int mt = 0; mt < 4; mt++)
                #pragma unroll
                for (int np = 0; np < 4; np++)
                    #pragma unroll
                    for (int h2 = 0; h2 < 2; h2++)
                        mma16816(acc[mt][np * 2 + h2], ah[mt],
                                 bh[np][h2 * 2], bh[np][h2 * 2 + 1]);
            #pragma unroll
            for (int mt = 0; mt < 4; mt++)
                #pragma unroll
                for (int np = 0; np < 4; np++)
                    #pragma unroll
                    for (int h2 = 0; h2 < 2; h2++)
                        mma16816(acc[mt][np * 2 + h2], ah[mt],
                                 bl[np][h2 * 2], bl[np][h2 * 2 + 1]);
            #pragma unroll
            for (int mt = 0; mt < 4; mt++)
                #pragma unroll
                for (int np = 0; np < 4; np++)
                    #pragma unroll
                    for (int h2 = 0; h2 < 2; h2++)
                        mma16816(acc[mt][np * 2 + h2], al2[mt],
                                 bh[np][h2 * 2], bh[np][h2 * 2 + 1]);
        }
    };

    issue(0);
    for (int c = 0; c < nchunks; c++) {
        asm volatile("cp.async.wait_group 0;" ::: "memory");
        __syncthreads();
        if (c + 1 < nchunks) issue(c + 1);
        compute(c & 1);
    }

    // ---- epilogue ----
    const int r0l = lane >> 2, c0l = (lane & 3) * 2;
    #pragma unroll
    for (int mt = 0; mt < 4; mt++) {
        const int rowA = bm + wm * 64 + mt * 16 + r0l;
        #pragma unroll
        for (int nt = 0; nt < 8; nt++) {
            const int col = bn + wn * 64 + nt * 8 + c0l;
            #pragma unroll
            for (int half = 0; half < 2; half++) {
                const int row = rowA + half * 8;
                float v0 = acc[mt][nt][half * 2 + 0];
                float v1 = acc[mt][nt][half * 2 + 1];
                if (EPI == 0) {
                    const float2 bb = *(const float2*)(bias + col);
                    v0 = tanhf(v0 + bb.x); v1 = tanhf(v1 + bb.y);
                    __nv_bfloat16 h0, l0, h1, l1;
                    split1(v0, h0, l0); split1(v1, h1, l1);
                    *(uint32_t*)(Chi + (size_t)row * N + col) = pk2(h0, h1);
                    *(uint32_t*)(Clo + (size_t)row * N + col) = pk2(l0, l1);
                } else {
                    *(float2*)(Cp + (size_t)row * N + col) = make_float2(v0, v1);
                }
            }
        }
    }
}

// ---------------------------------------------------------------------------
// Weight transpose + bf16 split: W[K][N] -> T_hi/T_lo[N][K]
// ---------------------------------------------------------------------------
__global__ void k_tsplit(const float* __restrict__ W,
                         __nv_bfloat16* __restrict__ Th,
                         __nv_bfloat16* __restrict__ Tl, int K, int N)
{
    __shared__ float t[32][33];
    const int n0 = blockIdx.x * 32, k0 = blockIdx.y * 32;
    for (int i = threadIdx.y; i < 32; i += 8)
        t[i][threadIdx.x] = W[(size_t)(k0 + i) * N + n0 + threadIdx.x];
    __syncthreads();
    for (int i = threadIdx.y; i < 32; i += 8) {
        float v = t[threadIdx.x][i];
        __nv_bfloat16 h, l;
        split1(v, h, l);
        size_t o = (size_t)(n0 + i) * K + k0 + threadIdx.x;
        Th[o] = h; Tl[o] = l;
    }
}

// ---------------------------------------------------------------------------
// Combine: dst = alpha*(p0+p1+bias) [+ addv], optional planes of dst
// ---------------------------------------------------------------------------
__global__ void k_comb(float4* __restrict__ dst,
                       const float4* __restrict__ p0, const float4* __restrict__ p1,
                       const float4* __restrict__ bias4,
                       const float4* __restrict__ addv, float alpha,
                       uint2* __restrict__ oh, uint2* __restrict__ ol)
{
    int i = blockIdx.x * 256 + threadIdx.x;
    float4 a = p0[i], b = p1[i], bb = bias4[i & 127];
    float4 v;
    v.x = alpha * (a.x + b.x + bb.x);
    v.y = alpha * (a.y + b.y + bb.y);
    v.z = alpha * (a.z + b.z + bb.z);
    v.w = alpha * (a.w + b.w + bb.w);
    if (addv) {
        float4 av = addv[i];
        v.x += av.x; v.y += av.y; v.z += av.z; v.w += av.w;
    }
    dst[i] = v;
    if (oh) {
        uint2 h2, l2; split4(v, h2, l2);
        oh[i] = h2; ol[i] = l2;
    }
}

// ---------------------------------------------------------------------------
// Elementwise kernels
// ---------------------------------------------------------------------------
__global__ void k_split(float4* __restrict__ o, uint2* __restrict__ oh,
                        uint2* __restrict__ ol, const float4* __restrict__ src)
{
    int i = blockIdx.x * 256 + threadIdx.x;
    float4 v = src[i];
    o[i] = v;
    uint2 h2, l2; split4(v, h2, l2);
    oh[i] = h2; ol[i] = l2;
}

__global__ void k_axpy(float4* __restrict__ o, const float4* __restrict__ y,
                       const float4* __restrict__ k, float a)
{
    int i = blockIdx.x * 256 + threadIdx.x;
    float4 yv = y[i], kv = k[i];
    o[i] = make_float4(fmaf(a, kv.x, yv.x), fmaf(a, kv.y, yv.y),
                       fmaf(a, kv.z, yv.z), fmaf(a, kv.w, yv.w));
}

__global__ void k_axpy_sp(uint2* __restrict__ oh, uint2* __restrict__ ol,
                          const float4* __restrict__ y,
                          const float4* __restrict__ k, float a)
{
    int i = blockIdx.x * 256 + threadIdx.x;
    float4 yv = y[i], kv = k[i];
    float4 v = make_float4(fmaf(a, kv.x, yv.x), fmaf(a, kv.y, yv.y),
                           fmaf(a, kv.z, yv.z), fmaf(a, kv.w, yv.w));
    uint2 h2, l2; split4(v, h2, l2);
    oh[i] = h2; ol[i] = l2;
}

__global__ void k_acc(float4* __restrict__ o, const float4* __restrict__ p, float a)
{
    int i = blockIdx.x * 256 + threadIdx.x;
    float4 ov = o[i], pv = p[i];
    o[i] = make_float4(fmaf(a, pv.x, ov.x), fmaf(a, pv.y, ov.y),
                       fmaf(a, pv.z, ov.z), fmaf(a, pv.w, ov.w));
}

__global__ void k_acc_sp(float4* __restrict__ o, const float4* __restrict__ p,
                         float a, uint2* __restrict__ oh, uint2* __restrict__ ol)
{
    int i = blockIdx.x * 256 + threadIdx.x;
    float4 ov = o[i], pv = p[i];
    float4 v = make_float4(fmaf(a, pv.x, ov.x), fmaf(a, pv.y, ov.y),
                           fmaf(a, pv.z, ov.z), fmaf(a, pv.w, ov.w));
    o[i] = v;
    uint2 h2, l2; split4(v, h2, l2);
    oh[i] = h2; ol[i] = l2;
}

__global__ void k_pred_sp(float4* __restrict__ o, const float4* __restrict__ y,
                          const float4* __restrict__ h0, const float4* __restrict__ h1,
                          const float4* __restrict__ h2, const float4* __restrict__ h3,
                          float c, uint2* __restrict__ oh, uint2* __restrict__ ol)
{
    int i = blockIdx.x * 256 + threadIdx.x;
    float4 yv = y[i], a = h0[i], b = h1[i], d = h2[i], e = h3[i];
    float4 r;
    r.x = yv.x + c * (55.f * a.x - 59.f * b.x + 37.f * d.x - 9.f * e.x);
    r.y = yv.y + c * (55.f * a.y - 59.f * b.y + 37.f * d.y - 9.f * e.y);
    r.z = yv.z + c * (55.f * a.z - 59.f * b.z + 37.f * d.z - 9.f * e.z);
    r.w = yv.w + c * (55.f * a.w - 59.f * b.w + 37.f * d.w - 9.f * e.w);
    o[i] = r;
    uint2 h2p, l2p; split4(r, h2p, l2p);
    oh[i] = h2p; ol[i] = l2p;
}

__global__ void k_base(float4* __restrict__ o, const float4* __restrict__ y,
                       const float4* __restrict__ h0, const float4* __restrict__ h1,
                       const float4* __restrict__ h2, float c)
{
    int i = blockIdx.x * 256 + threadIdx.x;
    float4 yv = y[i], a = h0[i], b = h1[i], d = h2[i];
    float4 r;
    r.x = yv.x + c * (19.f * a.x - 5.f * b.x + d.x);
    r.y = yv.y + c * (19.f * a.y - 5.f * b.y + d.y);
    r.z = yv.z + c * (19.f * a.z - 5.f * b.z + d.z);
    r.w = yv.w + c * (19.f * a.w - 5.f * b.w + d.w);
    o[i] = r;
}

// ---------------------------------------------------------------------------
// Host orchestration
// ---------------------------------------------------------------------------
extern "C" void kernel_launch(void* const* d_in, const int* in_sizes, int n_in,
                              void* d_out, int out_size)
{
    const float* x  = (const float*)d_in[0];
    const float* W1 = (const float*)d_in[1];
    const float* b1 = (const float*)d_in[2];
    const float* W2 = (const float*)d_in[3];
    const float* b2 = (const float*)d_in[4];
    float* out = (float*)d_out;

    float *y, *acc, *kk, *pred, *base, *histbase, *part;
    __nv_bfloat16 *pinh, *pinl, *w1h, *w1l, *w2h, *w2l, *ah, *al;
    cudaGetSymbolAddress((void**)&y,        g_y);
    cudaGetSymbolAddress((void**)&acc,      g_acc);
    cudaGetSymbolAddress((void**)&kk,       g_kk);
    cudaGetSymbolAddress((void**)&pred,     g_pred);
    cudaGetSymbolAddress((void**)&base,     g_base);
    cudaGetSymbolAddress((void**)&histbase, g_hist);
    cudaGetSymbolAddress((void**)&part,     g_part);
    cudaGetSymbolAddress((void**)&pinh,     g_pin_hi);
    cudaGetSymbolAddress((void**)&pinl,     g_pin_lo);
    cudaGetSymbolAddress((void**)&w1h,      g_w1t_hi);
    cudaGetSymbolAddress((void**)&w1l,      g_w1t_lo);
    cudaGetSymbolAddress((void**)&w2h,      g_w2t_hi);
    cudaGetSymbolAddress((void**)&w2l,      g_w2t_lo);
    cudaGetSymbolAddress((void**)&ah,       g_act_hi);
    cudaGetSymbolAddress((void**)&al,       g_act_lo);

    cudaFuncSetAttribute(gemm_cp<0>, cudaFuncAttributeMaxDynamicSharedMemorySize, GEMM_SMEM);
    cudaFuncSetAttribute(gemm_cp<1>, cudaFuncAttributeMaxDynamicSharedMemorySize, GEMM_SMEM);

    float* h[4];
    for (int i = 0; i < 4; i++) h[i] = histbase + (size_t)i * NSTATE;

    const float dt = 1.0f / (float)NSTEPS;
    const float c  = dt / 24.0f;

    const dim3 blk(256);
    const dim3 grid1(NH / 128, NB / 256);        // 16 x 16
    const dim3 grid2(ND / 128, NB / 256, 2);     // 4 x 16 x 2 (split-K)
    const int EG = NSTATE / 4 / 256;

    k_tsplit<<<dim3(NH / 32, ND / 32), dim3(32, 8)>>>(W1, w1h, w1l, ND, NH);
    k_tsplit<<<dim3(ND / 32, NH / 32), dim3(32, 8)>>>(W2, w2h, w2l, NH, ND);

    auto feval = [&](float* dstF, __nv_bfloat16* dsth, __nv_bfloat16* dstl,
                     float alpha, const float* addv) {
        gemm_cp<0><<<grid1, blk, GEMM_SMEM>>>(pinh, pinl, ND, w1h, w1l, ND,
                                              ND / 64, 0, b1, ah, al, nullptr, NH);
        gemm_cp<1><<<grid2, blk, GEMM_SMEM>>>(ah, al, NH, w2h, w2l, NH,
                                              (NH / 2) / 64, NH / 2, nullptr,
                                              nullptr, nullptr, part, ND);
        k_comb<<<EG, blk>>>((float4*)dstF, (const float4*)part,
                            (const float4*)(part + NSTATE), (const float4*)b2,
                            (const float4*)addv, alpha, (uint2*)dsth, (uint2*)dstl);
    };

    // y = x (fp32 + planes)
    k_split<<<EG, blk>>>((float4*)y, (uint2*)pinh, (uint2*)pinl, (const float4*)x);

    // ---- bootstrap: f(y0) -> h[3] ----
    feval(h[3], nullptr, nullptr, 1.f, nullptr);

    // ---- 3 RK4 steps; k1 reused from most recent hist entry ----
    for (int s = 0; s < 3; s++) {
        float* k1 = h[3 - s];
        k_axpy   <<<EG, blk>>>((float4*)acc, (const float4*)y, (const float4*)k1, dt / 6.f);
        k_axpy_sp<<<EG, blk>>>((uint2*)pinh, (uint2*)pinl,
                               (const float4*)y, (const float4*)k1, 0.5f * dt);
        feval(kk, nullptr, nullptr, 1.f, nullptr);                           // k2
        k_acc    <<<EG, blk>>>((float4*)acc, (const float4*)kk, dt / 3.f);
        k_axpy_sp<<<EG, blk>>>((uint2*)pinh, (uint2*)pinl,
                               (const float4*)y, (const float4*)kk, 0.5f * dt);
        feval(kk, nullptr, nullptr, 1.f, nullptr);                           // k3
        k_acc    <<<EG, blk>>>((float4*)acc, (const float4*)kk, dt / 3.f);
        k_axpy_sp<<<EG, blk>>>((uint2*)pinh, (uint2*)pinl,
                               (const float4*)y, (const float4*)kk, dt);
        feval(kk, nullptr, nullptr, 1.f, nullptr);                           // k4
        k_acc_sp <<<EG, blk>>>((float4*)acc, (const float4*)kk, dt / 6.f,
                               (uint2*)pinh, (uint2*)pinl);
        { float* t = y; y = acc; acc = t; }
        feval(h[2 - s], nullptr, nullptr, 1.f, nullptr);     // f(y_new) = next k1
    }

    // ---- 17 ABM4 predictor-corrector steps ----
    const int NABM = NSTEPS - 3;
    for (int i = 0; i < NABM; i++) {
        k_pred_sp<<<EG, blk>>>((float4*)pred, (const float4*)y,
                               (const float4*)h[0], (const float4*)h[1],
                               (const float4*)h[2], (const float4*)h[3], c,
                               (uint2*)pinh, (uint2*)pinl);
        k_base<<<EG, blk>>>((float4*)base, (const float4*)y,
                            (const float4*)h[0], (const float4*)h[1],
                            (const float4*)h[2], c);
        for (int j = 0; j < NCORR; j++) {
            const bool last = (i == NABM - 1) && (j == NCORR - 1);
            if (last) feval(out,  nullptr, nullptr, 9.f * c, base);
            else      feval(pred, pinh,    pinl,    9.f * c, base);
        }
        if (i < NABM - 1) {
            feval(h[3], nullptr, nullptr, 1.f, nullptr);     // f(pred)
            float* t = h[3]; h[3] = h[2]; h[2] = h[1]; h[1] = h[0]; h[0] = t;
            float* t2 = y; y = pred; pred = t2;
        }
    }
}

// round 11
// speedup vs baseline: 4.1613x; 1.3396x over previous
#include <cuda_runtime.h>
#include <cuda_fp16.h>
#include <cstdint>
#include <cstddef>

// ---------------------------------------------------------------------------
// Problem constants
// ---------------------------------------------------------------------------
constexpr int NB = 4096;
constexpr int ND = 512;
constexpr int NH = 2048;
constexpr int NSTATE = NB * ND;
constexpr int NSTEPS = 20;
constexpr int NCORR  = 3;

// ---------------------------------------------------------------------------
// Scratch (device globals)
// ---------------------------------------------------------------------------
__device__ float g_y[NSTATE];
__device__ float g_acc[NSTATE];
__device__ float g_kk[NSTATE];
__device__ float g_pred[NSTATE];
__device__ float g_base[NSTATE];
__device__ float g_hist[4 * NSTATE];
__device__ float g_part[2 * NSTATE];            // split-K partials for gemm2

__device__ __half g_pin_hi[NSTATE];             // feval input planes (fp16)
__device__ __half g_pin_lo[NSTATE];
__device__ __half g_w1t[(size_t)NH * ND];       // weights: single fp16 plane
__device__ __half g_w2t[(size_t)ND * NH];
__device__ __half g_act_hi[(size_t)NB * NH];
__device__ __half g_act_lo[(size_t)NB * NH];

// ---------------------------------------------------------------------------
// Helpers
// ---------------------------------------------------------------------------
__device__ __forceinline__ uint32_t smem_u32(const void* p) {
    uint32_t a;
    asm("{ .reg .u64 t; cvta.to.shared.u64 t, %1; cvt.u32.u64 %0, t; }"
        : "=r"(a) : "l"(p));
    return a;
}

__device__ __forceinline__ uint32_t swz(uint32_t o) {
    return o ^ ((o >> 3) & 0x70);
}

__device__ __forceinline__ void cpa16(uint32_t s, const void* g) {
    asm volatile("cp.async.cg.shared.global [%0], [%1], 16;" :: "r"(s), "l"(g));
}

__device__ __forceinline__ void ldmx4(uint32_t r[4], uint32_t addr) {
    asm volatile("ldmatrix.sync.aligned.m8n8.x4.shared.b16 {%0,%1,%2,%3}, [%4];"
                 : "=r"(r[0]), "=r"(r[1]), "=r"(r[2]), "=r"(r[3]) : "r"(addr));
}

__device__ __forceinline__ void mma16816(float d[4], const uint32_t a[4],
                                         uint32_t b0, uint32_t b1) {
    asm volatile(
        "mma.sync.aligned.m16n8k16.row.col.f32.f16.f16.f32 "
        "{%0,%1,%2,%3}, {%4,%5,%6,%7}, {%8,%9}, {%0,%1,%2,%3};"
        : "+f"(d[0]), "+f"(d[1]), "+f"(d[2]), "+f"(d[3])
        : "r"(a[0]), "r"(a[1]), "r"(a[2]), "r"(a[3]), "r"(b0), "r"(b1));
}

__device__ __forceinline__ uint32_t pk2h(__half a, __half b) {
    __half2 t = __halves2half2(a, b);
    return *reinterpret_cast<uint32_t*>(&t);
}
__device__ __forceinline__ void split1h(float v, __half& h, __half& l) {
    h = __float2half_rn(v);
    l = __float2half_rn(v - __half2float(h));
}
__device__ __forceinline__ void split4h(float4 v, uint2& oh, uint2& ol) {
    __half h0, h1, h2, h3, l0, l1, l2, l3;
    split1h(v.x, h0, l0); split1h(v.y, h1, l1);
    split1h(v.z, h2, l2); split1h(v.w, h3, l3);
    oh.x = pk2h(h0, h1); oh.y = pk2h(h2, h3);
    ol.x = pk2h(l0, l1); ol.y = pk2h(l2, l3);
}

// ---------------------------------------------------------------------------
// fp16 2-product split HMMA GEMM (A = hi+lo fp16 planes, B = single fp16).
// 2-stage cp.async, CTA tile 256x128, 8 warps of 64x64. Product-major MMAs.
//   EPI 0: C = tanh(acc + bias) -> fp16 hi/lo planes
//   EPI 1: partial fp32 store (split-K slice via blockIdx.z)
// SMEM/stage: A 2x32KB + B 16KB = 80KB; 2 stages = 160KB.
// ---------------------------------------------------------------------------
constexpr int STAGE_B = 81920;
constexpr int GEMM_SMEM = 2 * STAGE_B;   // 163840

template <int EPI>
__global__ __launch_bounds__(256, 1)
void gemm_cp(const __half* __restrict__ Ah,
             const __half* __restrict__ Al, int lda,
             const __half* __restrict__ Bp, int ldb,
             int nchunks, int kslice,
             const float* __restrict__ bias,
             __half* __restrict__ Chi,
             __half* __restrict__ Clo,
             float* __restrict__ Cp,
             int N)
{
    extern __shared__ char smem[];
    const uint32_t sbase = smem_u32(smem);
    const int tid = threadIdx.x;
    const int wid = tid >> 5, lane = tid & 31;
    const int wm = wid & 3;            // 4 row-blocks of 64
    const int wn = wid >> 2;           // 2 col-blocks of 64
    const int bm = blockIdx.y * 256, bn = blockIdx.x * 128;
    const int koff = blockIdx.z * kslice;
    if (EPI == 1) Cp += (size_t)blockIdx.z * NSTATE;

    // cp.async per-thread mapping
    const int cr = tid >> 3;
    const int cq = tid & 7;
    const uint32_t so0 = swz((uint32_t)cr * 128 + cq * 16);

    // incremental global pointers (advance 64 elems per chunk)
    const __half* pAh = Ah + (size_t)(bm + cr) * lda + koff + cq * 8;
    const __half* pAl = Al + (size_t)(bm + cr) * lda + koff + cq * 8;
    const __half* pB  = Bp + (size_t)(bn + cr) * ldb + koff + cq * 8;

    const int bg = lane >> 3;
    const uint32_t boffl = (uint32_t)((lane & 7) + ((bg & 2) ? 8 : 0)) * 128
                         + (bg & 1) * 16;
    const uint32_t aoffl = (uint32_t)(lane & 15) * 128 + (lane >> 4) * 16;

    float acc[4][8][4];
    #pragma unroll
    for (int mt = 0; mt < 4; mt++)
        #pragma unroll
        for (int nt = 0; nt < 8; nt++)
            #pragma unroll
            for (int q = 0; q < 4; q++) acc[mt][nt][q] = 0.f;

    auto issue = [&](int c) {
        const uint32_t s = sbase + (uint32_t)(c & 1) * STAGE_B;
        const int k0 = c << 6;
        #pragma unroll
        for (int i = 0; i < 8; i++) {            // A: 256 rows, 2 planes
            const uint32_t so = so0 + (uint32_t)i * 32 * 128;
            cpa16(s + so,         pAh + (size_t)i * 32 * lda + k0);
            cpa16(s + 32768 + so, pAl + (size_t)i * 32 * lda + k0);
        }
        #pragma unroll
        for (int i = 0; i < 4; i++) {            // B: 128 rows, 1 plane
            const uint32_t so = so0 + (uint32_t)i * 32 * 128;
            cpa16(s + 65536 + so, pB + (size_t)i * 32 * ldb + k0);
        }
        asm volatile("cp.async.commit_group;");
    };

    auto compute = [&](int st) {
        const uint32_t sa_h = sbase + (uint32_t)st * STAGE_B;
        const uint32_t sa_l = sa_h + 32768;
        const uint32_t sb   = sa_h + 65536;
        #pragma unroll
        for (int ks = 0; ks < 4; ks++) {
            const uint32_t kb = ks * 32;
            uint32_t ah[4][4], al2[4][4], bb[4][4];
            #pragma unroll
            for (int mt = 0; mt < 4; mt++) {
                const uint32_t o = aoffl + (uint32_t)(wm * 64 + mt * 16) * 128 + kb;
                ldmx4(ah[mt],  sa_h + swz(o));
                ldmx4(al2[mt], sa_l + swz(o));
            }
            #pragma unroll
            for (int np = 0; np < 4; np++) {
                const uint32_t o = boffl + (uint32_t)(wn * 64 + np * 16) * 128 + kb;
                ldmx4(bb[np], sb + swz(o));
            }
            // product-major: same-accumulator distance = 32 MMAs
            #pragma unroll
            for (int mt = 0; mt < 4; mt++)
                #pragma unroll
                for (int np = 0; np < 4; np++)
                    #pragma unroll
                    for (int h2 = 0; h2 < 2; h2++)
                        mma16816(acc[mt][np * 2 + h2], ah[mt],
                                 bb[np][h2 * 2], bb[np][h2 * 2 + 1]);
            #pragma unroll
            for (int mt = 0; mt < 4; mt++)
                #pragma unroll
                for (int np = 0; np < 4; np++)
                    #pragma unroll
                    for (int h2 = 0; h2 < 2; h2++)
                        mma16816(acc[mt][np * 2 + h2], al2[mt],
                                 bb[np][h2 * 2], bb[np][h2 * 2 + 1]);
        }
    };

    issue(0);
    for (int c = 0; c < nchunks; c++) {
        asm volatile("cp.async.wait_group 0;" ::: "memory");
        __syncthreads();
        if (c + 1 < nchunks) issue(c + 1);
        compute(c & 1);
    }

    // ---- epilogue ----
    const int r0l = lane >> 2, c0l = (lane & 3) * 2;
    #pragma unroll
    for (int mt = 0; mt < 4; mt++) {
        const int rowA = bm + wm * 64 + mt * 16 + r0l;
        #pragma unroll
        for (int nt = 0; nt < 8; nt++) {
            const int col = bn + wn * 64 + nt * 8 + c0l;
            #pragma unroll
            for (int half2i = 0; half2i < 2; half2i++) {
                const int row = rowA + half2i * 8;
                float v0 = acc[mt][nt][half2i * 2 + 0];
                float v1 = acc[mt][nt][half2i * 2 + 1];
                if (EPI == 0) {
                    const float2 bbv = *(const float2*)(bias + col);
                    v0 = tanhf(v0 + bbv.x); v1 = tanhf(v1 + bbv.y);
                    __half h0, l0, h1, l1;
                    split1h(v0, h0, l0); split1h(v1, h1, l1);
                    *(uint32_t*)(Chi + (size_t)row * N + col) = pk2h(h0, h1);
                    *(uint32_t*)(Clo + (size_t)row * N + col) = pk2h(l0, l1);
                } else {
                    *(float2*)(Cp + (size_t)row * N + col) = make_float2(v0, v1);
                }
            }
        }
    }
}

// ---------------------------------------------------------------------------
// Weight transpose to single fp16 plane: W[K][N] -> T[N][K]
// ---------------------------------------------------------------------------
__global__ void k_tsplit(const float* __restrict__ W,
                         __half* __restrict__ T, int K, int N)
{
    __shared__ float t[32][33];
    const int n0 = blockIdx.x * 32, k0 = blockIdx.y * 32;
    for (int i = threadIdx.y; i < 32; i += 8)
        t[i][threadIdx.x] = W[(size_t)(k0 + i) * N + n0 + threadIdx.x];
    __syncthreads();
    for (int i = threadIdx.y; i < 32; i += 8) {
        float v = t[threadIdx.x][i];
        T[(size_t)(n0 + i) * K + k0 + threadIdx.x] = __float2half_rn(v);
    }
}

// ---------------------------------------------------------------------------
// Combine: dst = alpha*(p0+p1+bias) [+ addv], optional fp16 planes of dst
// ---------------------------------------------------------------------------
__global__ void k_comb(float4* __restrict__ dst,
                       const float4* __restrict__ p0, const float4* __restrict__ p1,
                       const float4* __restrict__ bias4,
                       const float4* __restrict__ addv, float alpha,
                       uint2* __restrict__ oh, uint2* __restrict__ ol)
{
    int i = blockIdx.x * 256 + threadIdx.x;
    float4 a = p0[i], b = p1[i], bb = bias4[i & 127];
    float4 v;
    v.x = alpha * (a.x + b.x + bb.x);
    v.y = alpha * (a.y + b.y + bb.y);
    v.z = alpha * (a.z + b.z + bb.z);
    v.w = alpha * (a.w + b.w + bb.w);
    if (addv) {
        float4 av = addv[i];
        v.x += av.x; v.y += av.y; v.z += av.z; v.w += av.w;
    }
    dst[i] = v;
    if (oh) {
        uint2 h2, l2; split4h(v, h2, l2);
        oh[i] = h2; ol[i] = l2;
    }
}

// ---------------------------------------------------------------------------
// Elementwise kernels
// ---------------------------------------------------------------------------
__global__ void k_split(float4* __restrict__ o, uint2* __restrict__ oh,
                        uint2* __restrict__ ol, const float4* __restrict__ src)
{
    int i = blockIdx.x * 256 + threadIdx.x;
    float4 v = src[i];
    o[i] = v;
    uint2 h2, l2; split4h(v, h2, l2);
    oh[i] = h2; ol[i] = l2;
}

__global__ void k_axpy(float4* __restrict__ o, const float4* __restrict__ y,
                       const float4* __restrict__ k, float a)
{
    int i = blockIdx.x * 256 + threadIdx.x;
    float4 yv = y[i], kv = k[i];
    o[i] = make_float4(fmaf(a, kv.x, yv.x), fmaf(a, kv.y, yv.y),
                       fmaf(a, kv.z, yv.z), fmaf(a, kv.w, yv.w));
}

__global__ void k_axpy_sp(uint2* __restrict__ oh, uint2* __restrict__ ol,
                          const float4* __restrict__ y,
                          const float4* __restrict__ k, float a)
{
    int i = blockIdx.x * 256 + threadIdx.x;
    float4 yv = y[i], kv = k[i];
    float4 v = make_float4(fmaf(a, kv.x, yv.x), fmaf(a, kv.y, yv.y),
                           fmaf(a, kv.z, yv.z), fmaf(a, kv.w, yv.w));
    uint2 h2, l2; split4h(v, h2, l2);
    oh[i] = h2; ol[i] = l2;
}

__global__ void k_acc(float4* __restrict__ o, const float4* __restrict__ p, float a)
{
    int i = blockIdx.x * 256 + threadIdx.x;
    float4 ov = o[i], pv = p[i];
    o[i] = make_float4(fmaf(a, pv.x, ov.x), fmaf(a, pv.y, ov.y),
                       fmaf(a, pv.z, ov.z), fmaf(a, pv.w, ov.w));
}

__global__ void k_acc_sp(float4* __restrict__ o, const float4* __restrict__ p,
                         float a, uint2* __restrict__ oh, uint2* __restrict__ ol)
{
    int i = blockIdx.x * 256 + threadIdx.x;
    float4 ov = o[i], pv = p[i];
    float4 v = make_float4(fmaf(a, pv.x, ov.x), fmaf(a, pv.y, ov.y),
                           fmaf(a, pv.z, ov.z), fmaf(a, pv.w, ov.w));
    o[i] = v;
    uint2 h2, l2; split4h(v, h2, l2);
    oh[i] = h2; ol[i] = l2;
}

__global__ void k_pred_sp(float4* __restrict__ o, const float4* __restrict__ y,
                          const float4* __restrict__ h0, const float4* __restrict__ h1,
                          const float4* __restrict__ h2, const float4* __restrict__ h3,
                          float c, uint2* __restrict__ oh, uint2* __restrict__ ol)
{
    int i = blockIdx.x * 256 + threadIdx.x;
    float4 yv = y[i], a = h0[i], b = h1[i], d = h2[i], e = h3[i];
    float4 r;
    r.x = yv.x + c * (55.f * a.x - 59.f * b.x + 37.f * d.x - 9.f * e.x);
    r.y = yv.y + c * (55.f * a.y - 59.f * b.y + 37.f * d.y - 9.f * e.y);
    r.z = yv.z + c * (55.f * a.z - 59.f * b.z + 37.f * d.z - 9.f * e.z);
    r.w = yv.w + c * (55.f * a.w - 59.f * b.w + 37.f * d.w - 9.f * e.w);
    o[i] = r;
    uint2 h2p, l2p; split4h(r, h2p, l2p);
    oh[i] = h2p; ol[i] = l2p;
}

__global__ void k_base(float4* __restrict__ o, const float4* __restrict__ y,
                       const float4* __restrict__ h0, const float4* __restrict__ h1,
                       const float4* __restrict__ h2, float c)
{
    int i = blockIdx.x * 256 + threadIdx.x;
    float4 yv = y[i], a = h0[i], b = h1[i], d = h2[i];
    float4 r;
    r.x = yv.x + c * (19.f * a.x - 5.f * b.x + d.x);
    r.y = yv.y + c * (19.f * a.y - 5.f * b.y + d.y);
    r.z = yv.z + c * (19.f * a.z - 5.f * b.z + d.z);
    r.w = yv.w + c * (19.f * a.w - 5.f * b.w + d.w);
    o[i] = r;
}

// ---------------------------------------------------------------------------
// Host orchestration
// ---------------------------------------------------------------------------
extern "C" void kernel_launch(void* const* d_in, const int* in_sizes, int n_in,
                              void* d_out, int out_size)
{
    const float* x  = (const float*)d_in[0];
    const float* W1 = (const float*)d_in[1];
    const float* b1 = (const float*)d_in[2];
    const float* W2 = (const float*)d_in[3];
    const float* b2 = (const float*)d_in[4];
    float* out = (float*)d_out;

    float *y, *acc, *kk, *pred, *base, *histbase, *part;
    __half *pinh, *pinl, *w1t, *w2t, *ah, *al;
    cudaGetSymbolAddress((void**)&y,        g_y);
    cudaGetSymbolAddress((void**)&acc,      g_acc);
    cudaGetSymbolAddress((void**)&kk,       g_kk);
    cudaGetSymbolAddress((void**)&pred,     g_pred);
    cudaGetSymbolAddress((void**)&base,     g_base);
    cudaGetSymbolAddress((void**)&histbase, g_hist);
    cudaGetSymbolAddress((void**)&part,     g_part);
    cudaGetSymbolAddress((void**)&pinh,     g_pin_hi);
    cudaGetSymbolAddress((void**)&pinl,     g_pin_lo);
    cudaGetSymbolAddress((void**)&w1t,      g_w1t);
    cudaGetSymbolAddress((void**)&w2t,      g_w2t);
    cudaGetSymbolAddress((void**)&ah,       g_act_hi);
    cudaGetSymbolAddress((void**)&al,       g_act_lo);

    cudaFuncSetAttribute(gemm_cp<0>, cudaFuncAttributeMaxDynamicSharedMemorySize, GEMM_SMEM);
    cudaFuncSetAttribute(gemm_cp<1>, cudaFuncAttributeMaxDynamicSharedMemorySize, GEMM_SMEM);

    float* h[4];
    for (int i = 0; i < 4; i++) h[i] = histbase + (size_t)i * NSTATE;

    const float dt = 1.0f / (float)NSTEPS;
    const float c  = dt / 24.0f;

    const dim3 blk(256);
    const dim3 grid1(NH / 128, NB / 256);        // 16 x 16
    const dim3 grid2(ND / 128, NB / 256, 2);     // 4 x 16 x 2 (split-K)
    const int EG = NSTATE / 4 / 256;

    k_tsplit<<<dim3(NH / 32, ND / 32), dim3(32, 8)>>>(W1, w1t, ND, NH);
    k_tsplit<<<dim3(ND / 32, NH / 32), dim3(32, 8)>>>(W2, w2t, NH, ND);

    auto feval = [&](float* dstF, __half* dsth, __half* dstl,
                     float alpha, const float* addv) {
        gemm_cp<0><<<grid1, blk, GEMM_SMEM>>>(pinh, pinl, ND, w1t, ND,
                                              ND / 64, 0, b1, ah, al, nullptr, NH);
        gemm_cp<1><<<grid2, blk, GEMM_SMEM>>>(ah, al, NH, w2t, NH,
                                              (NH / 2) / 64, NH / 2, nullptr,
                                              nullptr, nullptr, part, ND);
        k_comb<<<EG, blk>>>((float4*)dstF, (const float4*)part,
                            (const float4*)(part + NSTATE), (const float4*)b2,
                            (const float4*)addv, alpha, (uint2*)dsth, (uint2*)dstl);
    };

    // y = x (fp32 + planes)
    k_split<<<EG, blk>>>((float4*)y, (uint2*)pinh, (uint2*)pinl, (const float4*)x);

    // ---- bootstrap: f(y0) -> h[3] ----
    feval(h[3], nullptr, nullptr, 1.f, nullptr);

    // ---- 3 RK4 steps; k1 reused from most recent hist entry ----
    for (int s = 0; s < 3; s++) {
        float* k1 = h[3 - s];
        k_axpy   <<<EG, blk>>>((float4*)acc, (const float4*)y, (const float4*)k1, dt / 6.f);
        k_axpy_sp<<<EG, blk>>>((uint2*)pinh, (uint2*)pinl,
                               (const float4*)y, (const float4*)k1, 0.5f * dt);
        feval(kk, nullptr, nullptr, 1.f, nullptr);                           // k2
        k_acc    <<<EG, blk>>>((float4*)acc, (const float4*)kk, dt / 3.f);
        k_axpy_sp<<<EG, blk>>>((uint2*)pinh, (uint2*)pinl,
                               (const float4*)y, (const float4*)kk, 0.5f * dt);
        feval(kk, nullptr, nullptr, 1.f, nullptr);                           // k3
        k_acc    <<<EG, blk>>>((float4*)acc, (const float4*)kk, dt / 3.f);
        k_axpy_sp<<<EG, blk>>>((uint2*)pinh, (uint2*)pinl,
                               (const float4*)y, (const float4*)kk, dt);
        feval(kk, nullptr, nullptr, 1.f, nullptr);                           // k4
        k_acc_sp <<<EG, blk>>>((float4*)acc, (const float4*)kk, dt / 6.f,
                               (uint2*)pinh, (uint2*)pinl);
        { float* t = y; y = acc; acc = t; }
        feval(h[2 - s], nullptr, nullptr, 1.f, nullptr);     // f(y_new) = next k1
    }

    // ---- 17 ABM4 predictor-corrector steps ----
    const int NABM = NSTEPS - 3;
    for (int i = 0; i < NABM; i++) {
        k_pred_sp<<<EG, blk>>>((float4*)pred, (const float4*)y,
                               (const float4*)h[0], (const float4*)h[1],
                               (const float4*)h[2], (const float4*)h[3], c,
                               (uint2*)pinh, (uint2*)pinl);
        k_base<<<EG, blk>>>((float4*)base, (const float4*)y,
                            (const float4*)h[0], (const float4*)h[1],
                            (const float4*)h[2], c);
        for (int j = 0; j < NCORR; j++) {
            const bool last = (i == NABM - 1) && (j == NCORR - 1);
            if (last) feval(out,  nullptr, nullptr, 9.f * c, base);
            else      feval(pred, pinh,    pinl,    9.f * c, base);
        }
        if (i < NABM - 1) {
            feval(h[3], nullptr, nullptr, 1.f, nullptr);     // f(pred)
            float* t = h[3]; h[3] = h[2]; h[2] = h[1]; h[1] = h[0]; h[0] = t;
            float* t2 = y; y = pred; pred = t2;
        }
    }
}

// round 13
// speedup vs baseline: 4.4390x; 1.0667x over previous
#include <cuda_runtime.h>
#include <cuda_fp16.h>
#include <cstdint>
#include <cstddef>

// ---------------------------------------------------------------------------
// Problem constants
// ---------------------------------------------------------------------------
constexpr int NB = 4096;
constexpr int ND = 512;
constexpr int NH = 2048;
constexpr int NSTATE = NB * ND;
constexpr int NSTEPS = 20;
constexpr int NCORR  = 3;

// ---------------------------------------------------------------------------
// Scratch (device globals)
// ---------------------------------------------------------------------------
__device__ float g_y[NSTATE];
__device__ float g_acc[NSTATE];
__device__ float g_kk[NSTATE];
__device__ float g_pred[NSTATE];
__device__ float g_base[NSTATE];
__device__ float g_hist[4 * NSTATE];
__device__ float g_part[2 * NSTATE];            // split-K partials for gemm2

__device__ __half g_pin_hi[NSTATE];             // feval input planes (fp16)
__device__ __half g_pin_lo[NSTATE];
__device__ __half g_w1t[(size_t)NH * ND];       // weights: single fp16 plane
__device__ __half g_w2t[(size_t)ND * NH];
__device__ __half g_act_hi[(size_t)NB * NH];
__device__ __half g_act_lo[(size_t)NB * NH];

// ---------------------------------------------------------------------------
// Helpers
// ---------------------------------------------------------------------------
__device__ __forceinline__ uint32_t smem_u32(const void* p) {
    uint32_t a;
    asm("{ .reg .u64 t; cvta.to.shared.u64 t, %1; cvt.u32.u64 %0, t; }"
        : "=r"(a) : "l"(p));
    return a;
}

__device__ __forceinline__ uint32_t swz(uint32_t o) {
    return o ^ ((o >> 3) & 0x70);
}

__device__ __forceinline__ void cpa16(uint32_t s, const void* g) {
    asm volatile("cp.async.cg.shared.global [%0], [%1], 16;" :: "r"(s), "l"(g));
}

__device__ __forceinline__ void ldmx4(uint32_t r[4], uint32_t addr) {
    asm volatile("ldmatrix.sync.aligned.m8n8.x4.shared.b16 {%0,%1,%2,%3}, [%4];"
                 : "=r"(r[0]), "=r"(r[1]), "=r"(r[2]), "=r"(r[3]) : "r"(addr));
}

__device__ __forceinline__ void mma16816(float d[4], const uint32_t a[4],
                                         uint32_t b0, uint32_t b1) {
    asm volatile(
        "mma.sync.aligned.m16n8k16.row.col.f32.f16.f16.f32 "
        "{%0,%1,%2,%3}, {%4,%5,%6,%7}, {%8,%9}, {%0,%1,%2,%3};"
        : "+f"(d[0]), "+f"(d[1]), "+f"(d[2]), "+f"(d[3])
        : "r"(a[0]), "r"(a[1]), "r"(a[2]), "r"(a[3]), "r"(b0), "r"(b1));
}

__device__ __forceinline__ uint32_t pk2h(__half a, __half b) {
    __half2 t = __halves2half2(a, b);
    return *reinterpret_cast<uint32_t*>(&t);
}
__device__ __forceinline__ void split1h(float v, __half& h, __half& l) {
    h = __float2half_rn(v);
    l = __float2half_rn(v - __half2float(h));
}
__device__ __forceinline__ void split4h(float4 v, uint2& oh, uint2& ol) {
    __half h0, h1, h2, h3, l0, l1, l2, l3;
    split1h(v.x, h0, l0); split1h(v.y, h1, l1);
    split1h(v.z, h2, l2); split1h(v.w, h3, l3);
    oh.x = pk2h(h0, h1); oh.y = pk2h(h2, h3);
    ol.x = pk2h(l0, l1); ol.y = pk2h(l2, l3);
}

// ---------------------------------------------------------------------------
// fp16 2-product split HMMA GEMM (A = hi+lo fp16 planes, B = single fp16).
// CTA tile 128x128, 8 warps of 32x64, 2 CTAs/SM (16 warps = 4/SMSP).
// 2-stage cp.async. Product-major MMA order.
//   EPI 0: C = tanh(acc + bias) -> fp16 hi/lo planes
//   EPI 1: partial fp32 store (split-K slice via blockIdx.z)
// SMEM/stage: A 2x16KB + B 16KB = 48KB; 2 stages = 96KB; x2 CTAs = 192KB/SM.
// ---------------------------------------------------------------------------
constexpr int STAGE_B = 49152;
constexpr int GEMM_SMEM = 2 * STAGE_B;   // 98304

template <int EPI>
__global__ __launch_bounds__(256, 2)
void gemm_cp(const __half* __restrict__ Ah,
             const __half* __restrict__ Al, int lda,
             const __half* __restrict__ Bp, int ldb,
             int nchunks, int kslice,
             const float* __restrict__ bias,
             __half* __restrict__ Chi,
             __half* __restrict__ Clo,
             float* __restrict__ Cp,
             int N)
{
    extern __shared__ char smem[];
    const uint32_t sbase = smem_u32(smem);
    const int tid = threadIdx.x;
    const int wid = tid >> 5, lane = tid & 31;
    const int wm = wid & 3;            // 4 row-blocks of 32
    const int wn = wid >> 2;           // 2 col-blocks of 64
    const int bm = blockIdx.y * 128, bn = blockIdx.x * 128;
    const int koff = blockIdx.z * kslice;
    if (EPI == 1) Cp += (size_t)blockIdx.z * NSTATE;

    // cp.async per-thread mapping: row cr (+i*32), 16B-col cq
    const int cr = tid >> 3;
    const int cq = tid & 7;
    const uint32_t so0 = swz((uint32_t)cr * 128 + cq * 16);

    // incremental global pointers
    const __half* pAh = Ah + (size_t)(bm + cr) * lda + koff + cq * 8;
    const __half* pAl = Al + (size_t)(bm + cr) * lda + koff + cq * 8;
    const __half* pB  = Bp + (size_t)(bn + cr) * ldb + koff + cq * 8;

    const int bg = lane >> 3;
    const uint32_t boffl = (uint32_t)((lane & 7) + ((bg & 2) ? 8 : 0)) * 128
                         + (bg & 1) * 16;
    const uint32_t aoffl = (uint32_t)(lane & 15) * 128 + (lane >> 4) * 16;

    float acc[2][8][4];
    #pragma unroll
    for (int mt = 0; mt < 2; mt++)
        #pragma unroll
        for (int nt = 0; nt < 8; nt++)
            #pragma unroll
            for (int q = 0; q < 4; q++) acc[mt][nt][q] = 0.f;

    auto issue = [&](int c) {
        const uint32_t s = sbase + (uint32_t)(c & 1) * STAGE_B;
        const int k0 = c << 6;
        #pragma unroll
        for (int i = 0; i < 4; i++) {            // A: 128 rows, 2 planes
            const uint32_t so = so0 + (uint32_t)i * 32 * 128;
            cpa16(s + so,         pAh + (size_t)i * 32 * lda + k0);
            cpa16(s + 16384 + so, pAl + (size_t)i * 32 * lda + k0);
        }
        #pragma unroll
        for (int i = 0; i < 4; i++) {            // B: 128 rows, 1 plane
            const uint32_t so = so0 + (uint32_t)i * 32 * 128;
            cpa16(s + 32768 + so, pB + (size_t)i * 32 * ldb + k0);
        }
        asm volatile("cp.async.commit_group;");
    };

    auto compute = [&](int st) {
        const uint32_t sa_h = sbase + (uint32_t)st * STAGE_B;
        const uint32_t sa_l = sa_h + 16384;
        const uint32_t sb   = sa_h + 32768;
        #pragma unroll
        for (int ks = 0; ks < 4; ks++) {
            const uint32_t kb = ks * 32;
            uint32_t ah[2][4], al2[2][4], bb[4][4];
            #pragma unroll
            for (int mt = 0; mt < 2; mt++) {
                const uint32_t o = aoffl + (uint32_t)(wm * 32 + mt * 16) * 128 + kb;
                ldmx4(ah[mt],  sa_h + swz(o));
                ldmx4(al2[mt], sa_l + swz(o));
            }
            #pragma unroll
            for (int np = 0; np < 4; np++) {
                const uint32_t o = boffl + (uint32_t)(wn * 64 + np * 16) * 128 + kb;
                ldmx4(bb[np], sb + swz(o));
            }
            // product-major: hi-product stream then lo-product stream
            #pragma unroll
            for (int mt = 0; mt < 2; mt++)
                #pragma unroll
                for (int np = 0; np < 4; np++)
                    #pragma unroll
                    for (int h2 = 0; h2 < 2; h2++)
                        mma16816(acc[mt][np * 2 + h2], ah[mt],
                                 bb[np][h2 * 2], bb[np][h2 * 2 + 1]);
            #pragma unroll
            for (int mt = 0; mt < 2; mt++)
                #pragma unroll
                for (int np = 0; np < 4; np++)
                    #pragma unroll
                    for (int h2 = 0; h2 < 2; h2++)
                        mma16816(acc[mt][np * 2 + h2], al2[mt],
                                 bb[np][h2 * 2], bb[np][h2 * 2 + 1]);
        }
    };

    issue(0);
    for (int c = 0; c < nchunks; c++) {
        asm volatile("cp.async.wait_group 0;" ::: "memory");
        __syncthreads();
        if (c + 1 < nchunks) issue(c + 1);
        compute(c & 1);
    }

    // ---- epilogue ----
    const int r0l = lane >> 2, c0l = (lane & 3) * 2;
    #pragma unroll
    for (int mt = 0; mt < 2; mt++) {
        const int rowA = bm + wm * 32 + mt * 16 + r0l;
        #pragma unroll
        for (int nt = 0; nt < 8; nt++) {
            const int col = bn + wn * 64 + nt * 8 + c0l;
            #pragma unroll
            for (int half2i = 0; half2i < 2; half2i++) {
                const int row = rowA + half2i * 8;
                float v0 = acc[mt][nt][half2i * 2 + 0];
                float v1 = acc[mt][nt][half2i * 2 + 1];
                if (EPI == 0) {
                    const float2 bbv = *(const float2*)(bias + col);
                    v0 = tanhf(v0 + bbv.x); v1 = tanhf(v1 + bbv.y);
                    __half h0, l0, h1, l1;
                    split1h(v0, h0, l0); split1h(v1, h1, l1);
                    *(uint32_t*)(Chi + (size_t)row * N + col) = pk2h(h0, h1);
                    *(uint32_t*)(Clo + (size_t)row * N + col) = pk2h(l0, l1);
                } else {
                    *(float2*)(Cp + (size_t)row * N + col) = make_float2(v0, v1);
                }
            }
        }
    }
}

// ---------------------------------------------------------------------------
// Weight transpose to single fp16 plane: W[K][N] -> T[N][K]
// ---------------------------------------------------------------------------
__global__ void k_tsplit(const float* __restrict__ W,
                         __half* __restrict__ T, int K, int N)
{
    __shared__ float t[32][33];
    const int n0 = blockIdx.x * 32, k0 = blockIdx.y * 32;
    for (int i = threadIdx.y; i < 32; i += 8)
        t[i][threadIdx.x] = W[(size_t)(k0 + i) * N + n0 + threadIdx.x];
    __syncthreads();
    for (int i = threadIdx.y; i < 32; i += 8) {
        float v = t[threadIdx.x][i];
        T[(size_t)(n0 + i) * K + k0 + threadIdx.x] = __float2half_rn(v);
    }
}

// ---------------------------------------------------------------------------
// Combine: dst = alpha*(p0+p1+bias) [+ addv], optional fp16 planes of dst
// ---------------------------------------------------------------------------
__global__ void k_comb(float4* __restrict__ dst,
                       const float4* __restrict__ p0, const float4* __restrict__ p1,
                       const float4* __restrict__ bias4,
                       const float4* __restrict__ addv, float alpha,
                       uint2* __restrict__ oh, uint2* __restrict__ ol)
{
    int i = blockIdx.x * 256 + threadIdx.x;
    float4 a = p0[i], b = p1[i], bb = bias4[i & 127];
    float4 v;
    v.x = alpha * (a.x + b.x + bb.x);
    v.y = alpha * (a.y + b.y + bb.y);
    v.z = alpha * (a.z + b.z + bb.z);
    v.w = alpha * (a.w + b.w + bb.w);
    if (addv) {
        float4 av = addv[i];
        v.x += av.x; v.y += av.y; v.z += av.z; v.w += av.w;
    }
    dst[i] = v;
    if (oh) {
        uint2 h2, l2; split4h(v, h2, l2);
        oh[i] = h2; ol[i] = l2;
    }
}

// ---------------------------------------------------------------------------
// Elementwise kernels
// ---------------------------------------------------------------------------
__global__ void k_split(float4* __restrict__ o, uint2* __restrict__ oh,
                        uint2* __restrict__ ol, const float4* __restrict__ src)
{
    int i = blockIdx.x * 256 + threadIdx.x;
    float4 v = src[i];
    o[i] = v;
    uint2 h2, l2; split4h(v, h2, l2);
    oh[i] = h2; ol[i] = l2;
}

__global__ void k_axpy(float4* __restrict__ o, const float4* __restrict__ y,
                       const float4* __restrict__ k, float a)
{
    int i = blockIdx.x * 256 + threadIdx.x;
    float4 yv = y[i], kv = k[i];
    o[i] = make_float4(fmaf(a, kv.x, yv.x), fmaf(a, kv.y, yv.y),
                       fmaf(a, kv.z, yv.z), fmaf(a, kv.w, yv.w));
}

__global__ void k_axpy_sp(uint2* __restrict__ oh, uint2* __restrict__ ol,
                          const float4* __restrict__ y,
                          const float4* __restrict__ k, float a)
{
    int i = blockIdx.x * 256 + threadIdx.x;
    float4 yv = y[i], kv = k[i];
    float4 v = make_float4(fmaf(a, kv.x, yv.x), fmaf(a, kv.y, yv.y),
                           fmaf(a, kv.z, yv.z), fmaf(a, kv.w, yv.w));
    uint2 h2, l2; split4h(v, h2, l2);
    oh[i] = h2; ol[i] = l2;
}

__global__ void k_acc(float4* __restrict__ o, const float4* __restrict__ p, float a)
{
    int i = blockIdx.x * 256 + threadIdx.x;
    float4 ov = o[i], pv = p[i];
    o[i] = make_float4(fmaf(a, pv.x, ov.x), fmaf(a, pv.y, ov.y),
                       fmaf(a, pv.z, ov.z), fmaf(a, pv.w, ov.w));
}

__global__ void k_acc_sp(float4* __restrict__ o, const float4* __restrict__ p,
                         float a, uint2* __restrict__ oh, uint2* __restrict__ ol)
{
    int i = blockIdx.x * 256 + threadIdx.x;
    float4 ov = o[i], pv = p[i];
    float4 v = make_float4(fmaf(a, pv.x, ov.x), fmaf(a, pv.y, ov.y),
                           fmaf(a, pv.z, ov.z), fmaf(a, pv.w, ov.w));
    o[i] = v;
    uint2 h2, l2; split4h(v, h2, l2);
    oh[i] = h2; ol[i] = l2;
}

__global__ void k_pred_sp(float4* __restrict__ o, const float4* __restrict__ y,
                          const float4* __restrict__ h0, const float4* __restrict__ h1,
                          const float4* __restrict__ h2, const float4* __restrict__ h3,
                          float c, uint2* __restrict__ oh, uint2* __restrict__ ol)
{
    int i = blockIdx.x * 256 + threadIdx.x;
    float4 yv = y[i], a = h0[i], b = h1[i], d = h2[i], e = h3[i];
    float4 r;
    r.x = yv.x + c * (55.f * a.x - 59.f * b.x + 37.f * d.x - 9.f * e.x);
    r.y = yv.y + c * (55.f * a.y - 59.f * b.y + 37.f * d.y - 9.f * e.y);
    r.z = yv.z + c * (55.f * a.z - 59.f * b.z + 37.f * d.z - 9.f * e.z);
    r.w = yv.w + c * (55.f * a.w - 59.f * b.w + 37.f * d.w - 9.f * e.w);
    o[i] = r;
    uint2 h2p, l2p; split4h(r, h2p, l2p);
    oh[i] = h2p; ol[i] = l2p;
}

__global__ void k_base(float4* __restrict__ o, const float4* __restrict__ y,
                       const float4* __restrict__ h0, const float4* __restrict__ h1,
                       const float4* __restrict__ h2, float c)
{
    int i = blockIdx.x * 256 + threadIdx.x;
    float4 yv = y[i], a = h0[i], b = h1[i], d = h2[i];
    float4 r;
    r.x = yv.x + c * (19.f * a.x - 5.f * b.x + d.x);
    r.y = yv.y + c * (19.f * a.y - 5.f * b.y + d.y);
    r.z = yv.z + c * (19.f * a.z - 5.f * b.z + d.z);
    r.w = yv.w + c * (19.f * a.w - 5.f * b.w + d.w);
    o[i] = r;
}

// ---------------------------------------------------------------------------
// Host orchestration
// ---------------------------------------------------------------------------
extern "C" void kernel_launch(void* const* d_in, const int* in_sizes, int n_in,
                              void* d_out, int out_size)
{
    const float* x  = (const float*)d_in[0];
    const float* W1 = (const float*)d_in[1];
    const float* b1 = (const float*)d_in[2];
    const float* W2 = (const float*)d_in[3];
    const float* b2 = (const float*)d_in[4];
    float* out = (float*)d_out;

    float *y, *acc, *kk, *pred, *base, *histbase, *part;
    __half *pinh, *pinl, *w1t, *w2t, *ah, *al;
    cudaGetSymbolAddress((void**)&y,        g_y);
    cudaGetSymbolAddress((void**)&acc,      g_acc);
    cudaGetSymbolAddress((void**)&kk,       g_kk);
    cudaGetSymbolAddress((void**)&pred,     g_pred);
    cudaGetSymbolAddress((void**)&base,     g_base);
    cudaGetSymbolAddress((void**)&histbase, g_hist);
    cudaGetSymbolAddress((void**)&part,     g_part);
    cudaGetSymbolAddress((void**)&pinh,     g_pin_hi);
    cudaGetSymbolAddress((void**)&pinl,     g_pin_lo);
    cudaGetSymbolAddress((void**)&w1t,      g_w1t);
    cudaGetSymbolAddress((void**)&w2t,      g_w2t);
    cudaGetSymbolAddress((void**)&ah,       g_act_hi);
    cudaGetSymbolAddress((void**)&al,       g_act_lo);

    cudaFuncSetAttribute(gemm_cp<0>, cudaFuncAttributeMaxDynamicSharedMemorySize, GEMM_SMEM);
    cudaFuncSetAttribute(gemm_cp<1>, cudaFuncAttributeMaxDynamicSharedMemorySize, GEMM_SMEM);

    float* h[4];
    for (int i = 0; i < 4; i++) h[i] = histbase + (size_t)i * NSTATE;

    const float dt = 1.0f / (float)NSTEPS;
    const float c  = dt / 24.0f;

    const dim3 blk(256);
    const dim3 grid1(NH / 128, NB / 128);        // 16 x 32 = 512 CTAs
    const dim3 grid2(ND / 128, NB / 128, 2);     // 4 x 32 x 2 = 256 CTAs
    const int EG = NSTATE / 4 / 256;

    k_tsplit<<<dim3(NH / 32, ND / 32), dim3(32, 8)>>>(W1, w1t, ND, NH);
    k_tsplit<<<dim3(ND / 32, NH / 32), dim3(32, 8)>>>(W2, w2t, NH, ND);

    auto feval = [&](float* dstF, __half* dsth, __half* dstl,
                     float alpha, const float* addv) {
        gemm_cp<0><<<grid1, blk, GEMM_SMEM>>>(pinh, pinl, ND, w1t, ND,
                                              ND / 64, 0, b1, ah, al, nullptr, NH);
        gemm_cp<1><<<grid2, blk, GEMM_SMEM>>>(ah, al, NH, w2t, NH,
                                              (NH / 2) / 64, NH / 2, nullptr,
                                              nullptr, nullptr, part, ND);
        k_comb<<<EG, blk>>>((float4*)dstF, (const float4*)part,
                            (const float4*)(part + NSTATE), (const float4*)b2,
                            (const float4*)addv, alpha, (uint2*)dsth, (uint2*)dstl);
    };

    // y = x (fp32 + planes)
    k_split<<<EG, blk>>>((float4*)y, (uint2*)pinh, (uint2*)pinl, (const float4*)x);

    // ---- bootstrap: f(y0) -> h[3] ----
    feval(h[3], nullptr, nullptr, 1.f, nullptr);

    // ---- 3 RK4 steps; k1 reused from most recent hist entry ----
    for (int s = 0; s < 3; s++) {
        float* k1 = h[3 - s];
        k_axpy   <<<EG, blk>>>((float4*)acc, (const float4*)y, (const float4*)k1, dt / 6.f);
        k_axpy_sp<<<EG, blk>>>((uint2*)pinh, (uint2*)pinl,
                               (const float4*)y, (const float4*)k1, 0.5f * dt);
        feval(kk, nullptr, nullptr, 1.f, nullptr);                           // k2
        k_acc    <<<EG, blk>>>((float4*)acc, (const float4*)kk, dt / 3.f);
        k_axpy_sp<<<EG, blk>>>((uint2*)pinh, (uint2*)pinl,
                               (const float4*)y, (const float4*)kk, 0.5f * dt);
        feval(kk, nullptr, nullptr, 1.f, nullptr);                           // k3
        k_acc    <<<EG, blk>>>((float4*)acc, (const float4*)kk, dt / 3.f);
        k_axpy_sp<<<EG, blk>>>((uint2*)pinh, (uint2*)pinl,
                               (const float4*)y, (const float4*)kk, dt);
        feval(kk, nullptr, nullptr, 1.f, nullptr);                           // k4
        k_acc_sp <<<EG, blk>>>((float4*)acc, (const float4*)kk, dt / 6.f,
                               (uint2*)pinh, (uint2*)pinl);
        { float* t = y; y = acc; acc = t; }
        feval(h[2 - s], nullptr, nullptr, 1.f, nullptr);     // f(y_new) = next k1
    }

    // ---- 17 ABM4 predictor-corrector steps ----
    const int NABM = NSTEPS - 3;
    for (int i = 0; i < NABM; i++) {
        k_pred_sp<<<EG, blk>>>((float4*)pred, (const float4*)y,
                               (const float4*)h[0], (const float4*)h[1],
                               (const float4*)h[2], (const float4*)h[3], c,
                               (uint2*)pinh, (uint2*)pinl);
        k_base<<<EG, blk>>>((float4*)base, (const float4*)y,
                            (const float4*)h[0], (const float4*)h[1],
                            (const float4*)h[2], c);
        for (int j = 0; j < NCORR; j++) {
            const bool last = (i == NABM - 1) && (j == NCORR - 1);
            if (last) feval(out,  nullptr, nullptr, 9.f * c, base);
            else      feval(pred, pinh,    pinl,    9.f * c, base);
        }
        if (i < NABM - 1) {
            feval(h[3], nullptr, nullptr, 1.f, nullptr);     // f(pred)
            float* t = h[3]; h[3] = h[2]; h[2] = h[1]; h[1] = h[0]; h[0] = t;
            float* t2 = y; y = pred; pred = t2;
        }
    }
}